// round 2
// baseline (speedup 1.0000x reference)
#include <cuda_runtime.h>
#include <math.h>
#include <stdint.h>

// Problem constants
#define T_TOK 4096
#define D_DIM 2048
#define E_NUM 16
#define I_DIM 1408
#define K_TOP 4
#define NPAIR (T_TOK * K_TOP)   // 16384

// -------- device scratch (no allocations allowed) --------
__device__ int g_count[E_NUM];
__device__ int g_fill[E_NUM];
__device__ int g_offset[E_NUM + 1];
__device__ int g_pairs[NPAIR];
__device__ float g_H[(size_t)NPAIR * I_DIM];   // ~92 MB intermediate silu(x@w0^T)*(x@w1^T)

// ---------------- routing ----------------
__global__ void k_init() {
    int i = threadIdx.x;
    if (i < E_NUM) { g_count[i] = 0; g_fill[i] = 0; }
}

__global__ void k_hist(const int* __restrict__ sel) {
    int p = blockIdx.x * blockDim.x + threadIdx.x;
    if (p < NPAIR) atomicAdd(&g_count[sel[p]], 1);
}

__global__ void k_scan() {
    int acc = 0;
    for (int e = 0; e < E_NUM; e++) { g_offset[e] = acc; acc += g_count[e]; }
    g_offset[E_NUM] = acc;
}

__global__ void k_fill(const int* __restrict__ sel) {
    int p = blockIdx.x * blockDim.x + threadIdx.x;
    if (p < NPAIR) {
        int e = sel[p];
        int pos = g_offset[e] + atomicAdd(&g_fill[e], 1);
        g_pairs[pos] = p;
    }
}

// ---------------- GEMM1: H = silu(X@W0^T) * (X@W1^T), grouped by expert ----------------
// Block tile: BM=128 rows (gathered tokens), BN1=64 cols (I dim), BK=16 over D=2048.
// 256 threads, each computes 8x4 micro-tile for BOTH matmuls (shared X tile).
#define BM   128
#define BN1  64
#define BKK  16

__global__ __launch_bounds__(256) void k_gemm1(
    const float* __restrict__ x,
    const float* __restrict__ w0,
    const float* __restrict__ w1)
{
    int e   = blockIdx.z;
    int cnt = g_count[e];
    int m0  = blockIdx.y * BM;
    if (m0 >= cnt) return;
    int n0   = blockIdx.x * BN1;
    int base = g_offset[e];

    __shared__ float Xs[BKK][BM];
    __shared__ float W0s[BKK][BN1];
    __shared__ float W1s[BKK][BN1];
    __shared__ int   rowTok[BM];

    int tid = threadIdx.x;
    if (tid < BM) {
        int r = m0 + tid;
        rowTok[tid] = (r < cnt) ? (g_pairs[base + r] / K_TOP) : -1;
    }
    __syncthreads();

    float acc0[8][4], acc1[8][4];
#pragma unroll
    for (int m = 0; m < 8; m++)
#pragma unroll
        for (int n = 0; n < 4; n++) { acc0[m][n] = 0.f; acc1[m][n] = 0.f; }

    const float* w0e = w0 + (size_t)e * I_DIM * D_DIM;
    const float* w1e = w1 + (size_t)e * I_DIM * D_DIM;

    int rg = tid >> 4;   // 0..15 (row group of 8)
    int cg = tid & 15;   // 0..15 (col group of 4)

    for (int k0 = 0; k0 < D_DIM; k0 += BKK) {
        // X tile: 128 rows x 16 cols = 512 float4 loads, 2 per thread
#pragma unroll
        for (int i = 0; i < 2; i++) {
            int idx = tid * 2 + i;
            int r   = idx >> 2;
            int c4  = idx & 3;
            int tok = rowTok[r];
            float4 v = make_float4(0.f, 0.f, 0.f, 0.f);
            if (tok >= 0)
                v = *(const float4*)(x + (size_t)tok * D_DIM + k0 + c4 * 4);
            Xs[c4 * 4 + 0][r] = v.x; Xs[c4 * 4 + 1][r] = v.y;
            Xs[c4 * 4 + 2][r] = v.z; Xs[c4 * 4 + 3][r] = v.w;
        }
        // W0/W1 tiles: 64 rows x 16 cols = 256 float4 each, 1 per thread per matrix
        {
            int n  = tid >> 2;
            int c4 = tid & 3;
            float4 a = *(const float4*)(w0e + (size_t)(n0 + n) * D_DIM + k0 + c4 * 4);
            W0s[c4 * 4 + 0][n] = a.x; W0s[c4 * 4 + 1][n] = a.y;
            W0s[c4 * 4 + 2][n] = a.z; W0s[c4 * 4 + 3][n] = a.w;
            float4 b = *(const float4*)(w1e + (size_t)(n0 + n) * D_DIM + k0 + c4 * 4);
            W1s[c4 * 4 + 0][n] = b.x; W1s[c4 * 4 + 1][n] = b.y;
            W1s[c4 * 4 + 2][n] = b.z; W1s[c4 * 4 + 3][n] = b.w;
        }
        __syncthreads();

#pragma unroll
        for (int k = 0; k < BKK; k++) {
            float xf[8], wa[4], wb[4];
            *(float4*)&xf[0] = *(const float4*)&Xs[k][rg * 8];
            *(float4*)&xf[4] = *(const float4*)&Xs[k][rg * 8 + 4];
            *(float4*)&wa[0] = *(const float4*)&W0s[k][cg * 4];
            *(float4*)&wb[0] = *(const float4*)&W1s[k][cg * 4];
#pragma unroll
            for (int m = 0; m < 8; m++)
#pragma unroll
                for (int n = 0; n < 4; n++) {
                    acc0[m][n] = fmaf(xf[m], wa[n], acc0[m][n]);
                    acc1[m][n] = fmaf(xf[m], wb[n], acc1[m][n]);
                }
        }
        __syncthreads();
    }

    // epilogue: H = silu(acc0) * acc1
#pragma unroll
    for (int m = 0; m < 8; m++) {
        int r = m0 + rg * 8 + m;
        if (r < cnt) {
            float out4[4];
#pragma unroll
            for (int n = 0; n < 4; n++) {
                float a = acc0[m][n];
                float s = a / (1.f + __expf(-a));
                out4[n] = s * acc1[m][n];
            }
            *(float4*)(g_H + (size_t)(base + r) * I_DIM + n0 + cg * 4) = *(float4*)out4;
        }
    }
}

// ---------------- GEMM2: OUT[pair, :] = (H @ W2^T) * rw[pair] ----------------
// Block tile: BM=128 rows, BN2=128 cols (D dim), BK=16 over I=1408.
// 256 threads, 8x8 micro-tile.
#define BN2 128

__global__ __launch_bounds__(256) void k_gemm2(
    const float* __restrict__ w2,
    const float* __restrict__ rw,
    float* __restrict__ out)
{
    int e   = blockIdx.z;
    int cnt = g_count[e];
    int m0  = blockIdx.y * BM;
    if (m0 >= cnt) return;
    int n0   = blockIdx.x * BN2;
    int base = g_offset[e];

    __shared__ float Hs[BKK][BM];
    __shared__ float Ws[BKK][BN2];
    __shared__ int   rowPair[BM];

    int tid = threadIdx.x;
    if (tid < BM) {
        int r = m0 + tid;
        rowPair[tid] = (r < cnt) ? g_pairs[base + r] : -1;
    }
    __syncthreads();

    float acc[8][8];
#pragma unroll
    for (int m = 0; m < 8; m++)
#pragma unroll
        for (int n = 0; n < 8; n++) acc[m][n] = 0.f;

    const float* w2e = w2 + (size_t)e * D_DIM * I_DIM;

    int rg = tid >> 4;   // 0..15
    int cg = tid & 15;   // 0..15

    for (int k0 = 0; k0 < I_DIM; k0 += BKK) {
        // H tile: 128 rows x 16 cols = 512 float4, 2 per thread
#pragma unroll
        for (int i = 0; i < 2; i++) {
            int idx = tid * 2 + i;
            int r   = idx >> 2;
            int c4  = idx & 3;
            int rg_g = m0 + r;
            float4 v = make_float4(0.f, 0.f, 0.f, 0.f);
            if (rg_g < cnt)
                v = *(const float4*)(g_H + (size_t)(base + rg_g) * I_DIM + k0 + c4 * 4);
            Hs[c4 * 4 + 0][r] = v.x; Hs[c4 * 4 + 1][r] = v.y;
            Hs[c4 * 4 + 2][r] = v.z; Hs[c4 * 4 + 3][r] = v.w;
        }
        // W2 tile: 128 rows x 16 cols = 512 float4, 2 per thread
#pragma unroll
        for (int i = 0; i < 2; i++) {
            int idx = tid * 2 + i;
            int n   = idx >> 2;
            int c4  = idx & 3;
            float4 a = *(const float4*)(w2e + (size_t)(n0 + n) * I_DIM + k0 + c4 * 4);
            Ws[c4 * 4 + 0][n] = a.x; Ws[c4 * 4 + 1][n] = a.y;
            Ws[c4 * 4 + 2][n] = a.z; Ws[c4 * 4 + 3][n] = a.w;
        }
        __syncthreads();

#pragma unroll
        for (int k = 0; k < BKK; k++) {
            float hf[8], wf[8];
            *(float4*)&hf[0] = *(const float4*)&Hs[k][rg * 8];
            *(float4*)&hf[4] = *(const float4*)&Hs[k][rg * 8 + 4];
            *(float4*)&wf[0] = *(const float4*)&Ws[k][cg * 8];
            *(float4*)&wf[4] = *(const float4*)&Ws[k][cg * 8 + 4];
#pragma unroll
            for (int m = 0; m < 8; m++)
#pragma unroll
                for (int n = 0; n < 8; n++)
                    acc[m][n] = fmaf(hf[m], wf[n], acc[m][n]);
        }
        __syncthreads();
    }

    // epilogue: scale by routing weight, scatter to out[pair * D + d]
#pragma unroll
    for (int m = 0; m < 8; m++) {
        int r = m0 + rg * 8 + m;
        if (r < cnt) {
            int pair = rowPair[rg * 8 + m];
            float w = rw[pair];
            float o[8];
#pragma unroll
            for (int n = 0; n < 8; n++) o[n] = acc[m][n] * w;
            float* op = out + (size_t)pair * D_DIM + n0 + cg * 8;
            *(float4*)(op)     = *(float4*)&o[0];
            *(float4*)(op + 4) = *(float4*)&o[4];
        }
    }
}

// ---------------- launch ----------------
extern "C" void kernel_launch(void* const* d_in, const int* in_sizes, int n_in,
                              void* d_out, int out_size)
{
    const float* x   = (const float*)d_in[0];
    const float* w0  = (const float*)d_in[1];
    const float* w1  = (const float*)d_in[2];
    const float* w2  = (const float*)d_in[3];
    const int*   sel = (const int*)d_in[4];
    const float* rw  = (const float*)d_in[5];
    float* out = (float*)d_out;

    k_init<<<1, 32>>>();
    k_hist<<<NPAIR / 256, 256>>>(sel);
    k_scan<<<1, 1>>>();
    k_fill<<<NPAIR / 256, 256>>>(sel);

    // 32 M-tiles per expert covers up to 4096 rows/expert (avg is 1024; binomial
    // tail makes >4096 impossible in practice). Empty tiles exit immediately.
    dim3 g1(I_DIM / BN1, 32, E_NUM);
    k_gemm1<<<g1, 256>>>(x, w0, w1);

    dim3 g2(D_DIM / BN2, 32, E_NUM);
    k_gemm2<<<g2, 256>>>(w2, rw, out);
}

// round 5
// speedup vs baseline: 4.5913x; 4.5913x over previous
#include <cuda_runtime.h>
#include <math.h>
#include <stdint.h>

// Problem constants
#define T_TOK 4096
#define D_DIM 2048
#define E_NUM 16
#define I_DIM 1408
#define K_TOP 4
#define NPAIR (T_TOK * K_TOP)   // 16384

// -------- device scratch --------
__device__ int g_count[E_NUM];
__device__ int g_fill[E_NUM];
__device__ int g_offset[E_NUM + 1];
__device__ int g_pairs[NPAIR];
__device__ float g_H[(size_t)NPAIR * I_DIM];   // ~92 MB intermediate

// ---------------- routing ----------------
__global__ void k_init() {
    int i = threadIdx.x;
    if (i < E_NUM) { g_count[i] = 0; g_fill[i] = 0; }
}
__global__ void k_hist(const int* __restrict__ sel) {
    int p = blockIdx.x * blockDim.x + threadIdx.x;
    if (p < NPAIR) atomicAdd(&g_count[sel[p]], 1);
}
__global__ void k_scan() {
    int acc = 0;
    for (int e = 0; e < E_NUM; e++) { g_offset[e] = acc; acc += g_count[e]; }
    g_offset[E_NUM] = acc;
}
__global__ void k_fill(const int* __restrict__ sel) {
    int p = blockIdx.x * blockDim.x + threadIdx.x;
    if (p < NPAIR) {
        int e = sel[p];
        int pos = g_offset[e] + atomicAdd(&g_fill[e], 1);
        g_pairs[pos] = p;
    }
}

// ---------------- helpers ----------------
__device__ __forceinline__ uint32_t f2tf(float f) {
    uint32_t u;
    asm("cvt.rna.tf32.f32 %0, %1;" : "=r"(u) : "f"(f));
    return u;
}
__device__ __forceinline__ void mma8(float* d, const uint32_t* a, const uint32_t* b) {
    asm volatile(
        "mma.sync.aligned.m16n8k8.row.col.f32.tf32.tf32.f32 "
        "{%0,%1,%2,%3}, {%4,%5,%6,%7}, {%8,%9}, {%0,%1,%2,%3};"
        : "+f"(d[0]), "+f"(d[1]), "+f"(d[2]), "+f"(d[3])
        : "r"(a[0]), "r"(a[1]), "r"(a[2]), "r"(a[3]), "r"(b[0]), "r"(b[1]));
}

// ---------------- tiling ----------------
#define BM   128
#define BK   32
#define LDS  36                       // padded row stride (floats): conflict-free frags
#define ROWSM 128                     // rows per smem matrix (A and B both 128)
#define STAGE_F (2 * ROWSM * LDS)     // floats per stage (A+B)
#define SMEM_F  (2 * STAGE_F)         // two stages
#define SMEM_B  (SMEM_F * 4)          // 73728 bytes

// =====================================================================
// GEMM1: D0 = X@W0^T, D1 = X@W1^T (shared X), H = silu(D0)*D1
// Block: 128 rows x 64 I-cols (both matrices). B smem = [W0 64 rows | W1 64 rows].
// 8 warps: wr=wid&1 (m half), wc=wid>>1 (16-col group). Warp owns D0 cols
// [16wc,16wc+16) AND D1 same cols -> silu pairing is warp-local.
// =====================================================================
__global__ __launch_bounds__(256, 1)
void k_gemm1(const float* __restrict__ x,
             const float* __restrict__ w0,
             const float* __restrict__ w1)
{
    extern __shared__ uint32_t sm[];
    __shared__ int rowTok[BM];

    int e   = blockIdx.z;
    int cnt = g_count[e];
    int m0  = blockIdx.y * BM;
    if (m0 >= cnt) return;
    int n0   = blockIdx.x * 64;
    int base = g_offset[e];

    int tid  = threadIdx.x;
    int wid  = tid >> 5;
    int lane = tid & 31;
    int g    = lane >> 2;
    int t    = lane & 3;
    int wr   = wid & 1;
    int wc   = wid >> 1;

    if (tid < BM) {
        int r = m0 + tid;
        rowTok[tid] = (r < cnt) ? (g_pairs[base + r] / K_TOP) : -1;
    }
    __syncthreads();

    const float* w0e = w0 + (size_t)e * I_DIM * D_DIM;
    const float* w1e = w1 + (size_t)e * I_DIM * D_DIM;

    // per-thread producer descriptors: 4 A-rows + 4 B-rows, fixed all stages
    const float* pX[4];
    const float* pW[4];
    bool vX[4];
    int soff[4];
#pragma unroll
    for (int i = 0; i < 4; i++) {
        int idx = i * 256 + tid;
        int row = idx >> 3;
        int c4  = idx & 7;
        soff[i] = row * LDS + c4 * 4;
        int tok = rowTok[row];
        vX[i] = (tok >= 0);
        pX[i] = x + (size_t)(vX[i] ? tok : 0) * D_DIM + c4 * 4;
        pW[i] = (row < 64)
              ? (w0e + (size_t)(n0 + row) * D_DIM + c4 * 4)
              : (w1e + (size_t)(n0 + row - 64) * D_DIM + c4 * 4);
    }

    float acc[4][4][4];
#pragma unroll
    for (int mi = 0; mi < 4; mi++)
#pragma unroll
        for (int ni = 0; ni < 4; ni++)
#pragma unroll
            for (int q = 0; q < 4; q++) acc[mi][ni][q] = 0.f;

    const int nbase[4] = {16 * wc, 16 * wc + 8, 64 + 16 * wc, 64 + 16 * wc + 8};

    float4 rx[4], rv[4];
    // prologue: stage 0
#pragma unroll
    for (int i = 0; i < 4; i++) {
        rx[i] = vX[i] ? *(const float4*)pX[i] : make_float4(0, 0, 0, 0);
        rv[i] = *(const float4*)pW[i];
    }
    {
        uint32_t* Ad = sm;
        uint32_t* Bd = sm + ROWSM * LDS;
#pragma unroll
        for (int i = 0; i < 4; i++) {
            Ad[soff[i] + 0] = f2tf(rx[i].x); Ad[soff[i] + 1] = f2tf(rx[i].y);
            Ad[soff[i] + 2] = f2tf(rx[i].z); Ad[soff[i] + 3] = f2tf(rx[i].w);
            Bd[soff[i] + 0] = f2tf(rv[i].x); Bd[soff[i] + 1] = f2tf(rv[i].y);
            Bd[soff[i] + 2] = f2tf(rv[i].z); Bd[soff[i] + 3] = f2tf(rv[i].w);
        }
    }
    __syncthreads();

    const int NCHUNK = D_DIM / BK;  // 64
    for (int c = 0; c < NCHUNK; c++) {
        int cur = c & 1;
        if (c + 1 < NCHUNK) {
            int ko = (c + 1) * BK;
#pragma unroll
            for (int i = 0; i < 4; i++) {
                rx[i] = vX[i] ? *(const float4*)(pX[i] + ko) : make_float4(0, 0, 0, 0);
                rv[i] = *(const float4*)(pW[i] + ko);
            }
        }
        const uint32_t* As = sm + cur * STAGE_F;
        const uint32_t* Bs = As + ROWSM * LDS;
#pragma unroll
        for (int s = 0; s < 4; s++) {
            int kk = s * 8;
            uint32_t a[4][4], b[4][2];
#pragma unroll
            for (int mi = 0; mi < 4; mi++) {
                int r = (wr * 64 + mi * 16 + g) * LDS + kk + t;
                a[mi][0] = As[r];
                a[mi][1] = As[r + 8 * LDS];
                a[mi][2] = As[r + 4];
                a[mi][3] = As[r + 8 * LDS + 4];
            }
#pragma unroll
            for (int ni = 0; ni < 4; ni++) {
                int r = (nbase[ni] + g) * LDS + kk + t;
                b[ni][0] = Bs[r];
                b[ni][1] = Bs[r + 4];
            }
#pragma unroll
            for (int mi = 0; mi < 4; mi++)
#pragma unroll
                for (int ni = 0; ni < 4; ni++)
                    mma8(acc[mi][ni], a[mi], b[ni]);
        }
        if (c + 1 < NCHUNK) {
            uint32_t* Ad = sm + (cur ^ 1) * STAGE_F;
            uint32_t* Bd = Ad + ROWSM * LDS;
#pragma unroll
            for (int i = 0; i < 4; i++) {
                Ad[soff[i] + 0] = f2tf(rx[i].x); Ad[soff[i] + 1] = f2tf(rx[i].y);
                Ad[soff[i] + 2] = f2tf(rx[i].z); Ad[soff[i] + 3] = f2tf(rx[i].w);
                Bd[soff[i] + 0] = f2tf(rv[i].x); Bd[soff[i] + 1] = f2tf(rv[i].y);
                Bd[soff[i] + 2] = f2tf(rv[i].z); Bd[soff[i] + 3] = f2tf(rv[i].w);
            }
        }
        __syncthreads();
    }

    // epilogue: H = silu(D0) * D1   (pairs: ni and ni+2)
#pragma unroll
    for (int mi = 0; mi < 4; mi++) {
#pragma unroll
        for (int jj = 0; jj < 2; jj++) {
            int col = n0 + 16 * wc + 8 * jj + 2 * t;
            float* d0 = acc[mi][jj];
            float* d1 = acc[mi][jj + 2];
            int r0 = wr * 64 + mi * 16 + g;
            if (m0 + r0 < cnt) {
                float h0 = (d0[0] / (1.f + __expf(-d0[0]))) * d1[0];
                float h1 = (d0[1] / (1.f + __expf(-d0[1]))) * d1[1];
                *(float2*)(g_H + (size_t)(base + m0 + r0) * I_DIM + col) = make_float2(h0, h1);
            }
            int r1 = r0 + 8;
            if (m0 + r1 < cnt) {
                float h0 = (d0[2] / (1.f + __expf(-d0[2]))) * d1[2];
                float h1 = (d0[3] / (1.f + __expf(-d0[3]))) * d1[3];
                *(float2*)(g_H + (size_t)(base + m0 + r1) * I_DIM + col) = make_float2(h0, h1);
            }
        }
    }
}

// =====================================================================
// GEMM2: OUT[pair,:] = (H @ W2^T) * rw[pair].  Block 128 x 128, warp 64x32.
// =====================================================================
__global__ __launch_bounds__(256, 1)
void k_gemm2(const float* __restrict__ w2,
             const float* __restrict__ rw,
             float* __restrict__ out)
{
    extern __shared__ uint32_t sm[];
    __shared__ int rowPair[BM];

    int e   = blockIdx.z;
    int cnt = g_count[e];
    int m0  = blockIdx.y * BM;
    if (m0 >= cnt) return;
    int n0   = blockIdx.x * 128;
    int base = g_offset[e];

    int tid  = threadIdx.x;
    int wid  = tid >> 5;
    int lane = tid & 31;
    int g    = lane >> 2;
    int t    = lane & 3;
    int wr   = wid & 1;
    int wc   = wid >> 1;

    if (tid < BM) {
        int r = m0 + tid;
        rowPair[tid] = (r < cnt) ? g_pairs[base + r] : -1;
    }
    __syncthreads();

    const float* w2e = w2 + (size_t)e * D_DIM * I_DIM;

    const float* pH[4];
    const float* pW[4];
    bool vH[4];
    int soff[4];
#pragma unroll
    for (int i = 0; i < 4; i++) {
        int idx = i * 256 + tid;
        int row = idx >> 3;
        int c4  = idx & 7;
        soff[i] = row * LDS + c4 * 4;
        int gr  = m0 + row;
        vH[i] = (gr < cnt);
        pH[i] = g_H + (size_t)(base + (vH[i] ? gr : 0)) * I_DIM + c4 * 4;
        pW[i] = w2e + (size_t)(n0 + row) * I_DIM + c4 * 4;
    }

    float acc[4][4][4];
#pragma unroll
    for (int mi = 0; mi < 4; mi++)
#pragma unroll
        for (int ni = 0; ni < 4; ni++)
#pragma unroll
            for (int q = 0; q < 4; q++) acc[mi][ni][q] = 0.f;

    float4 rx[4], rv[4];
#pragma unroll
    for (int i = 0; i < 4; i++) {
        rx[i] = vH[i] ? *(const float4*)pH[i] : make_float4(0, 0, 0, 0);
        rv[i] = *(const float4*)pW[i];
    }
    {
        uint32_t* Ad = sm;
        uint32_t* Bd = sm + ROWSM * LDS;
#pragma unroll
        for (int i = 0; i < 4; i++) {
            Ad[soff[i] + 0] = f2tf(rx[i].x); Ad[soff[i] + 1] = f2tf(rx[i].y);
            Ad[soff[i] + 2] = f2tf(rx[i].z); Ad[soff[i] + 3] = f2tf(rx[i].w);
            Bd[soff[i] + 0] = f2tf(rv[i].x); Bd[soff[i] + 1] = f2tf(rv[i].y);
            Bd[soff[i] + 2] = f2tf(rv[i].z); Bd[soff[i] + 3] = f2tf(rv[i].w);
        }
    }
    __syncthreads();

    const int NCHUNK = I_DIM / BK;  // 44
    for (int c = 0; c < NCHUNK; c++) {
        int cur = c & 1;
        if (c + 1 < NCHUNK) {
            int ko = (c + 1) * BK;
#pragma unroll
            for (int i = 0; i < 4; i++) {
                rx[i] = vH[i] ? *(const float4*)(pH[i] + ko) : make_float4(0, 0, 0, 0);
                rv[i] = *(const float4*)(pW[i] + ko);
            }
        }
        const uint32_t* As = sm + cur * STAGE_F;
        const uint32_t* Bs = As + ROWSM * LDS;
#pragma unroll
        for (int s = 0; s < 4; s++) {
            int kk = s * 8;
            uint32_t a[4][4], b[4][2];
#pragma unroll
            for (int mi = 0; mi < 4; mi++) {
                int r = (wr * 64 + mi * 16 + g) * LDS + kk + t;
                a[mi][0] = As[r];
                a[mi][1] = As[r + 8 * LDS];
                a[mi][2] = As[r + 4];
                a[mi][3] = As[r + 8 * LDS + 4];
            }
#pragma unroll
            for (int ni = 0; ni < 4; ni++) {
                int r = (32 * wc + 8 * ni + g) * LDS + kk + t;
                b[ni][0] = Bs[r];
                b[ni][1] = Bs[r + 4];
            }
#pragma unroll
            for (int mi = 0; mi < 4; mi++)
#pragma unroll
                for (int ni = 0; ni < 4; ni++)
                    mma8(acc[mi][ni], a[mi], b[ni]);
        }
        if (c + 1 < NCHUNK) {
            uint32_t* Ad = sm + (cur ^ 1) * STAGE_F;
            uint32_t* Bd = Ad + ROWSM * LDS;
#pragma unroll
            for (int i = 0; i < 4; i++) {
                Ad[soff[i] + 0] = f2tf(rx[i].x); Ad[soff[i] + 1] = f2tf(rx[i].y);
                Ad[soff[i] + 2] = f2tf(rx[i].z); Ad[soff[i] + 3] = f2tf(rx[i].w);
                Bd[soff[i] + 0] = f2tf(rv[i].x); Bd[soff[i] + 1] = f2tf(rv[i].y);
                Bd[soff[i] + 2] = f2tf(rv[i].z); Bd[soff[i] + 3] = f2tf(rv[i].w);
            }
        }
        __syncthreads();
    }

    // epilogue: scale by routing weight, scatter to out[pair]
#pragma unroll
    for (int mi = 0; mi < 4; mi++) {
        int r0 = wr * 64 + mi * 16 + g;
#pragma unroll
        for (int half = 0; half < 2; half++) {
            int r = r0 + half * 8;
            if (m0 + r < cnt) {
                int pair = rowPair[r];
                float w  = rw[pair];
                float* op = out + (size_t)pair * D_DIM + n0;
#pragma unroll
                for (int ni = 0; ni < 4; ni++) {
                    int col = 32 * wc + 8 * ni + 2 * t;
                    float v0 = acc[mi][ni][half * 2 + 0] * w;
                    float v1 = acc[mi][ni][half * 2 + 1] * w;
                    *(float2*)(op + col) = make_float2(v0, v1);
                }
            }
        }
    }
}

// ---------------- launch ----------------
extern "C" void kernel_launch(void* const* d_in, const int* in_sizes, int n_in,
                              void* d_out, int out_size)
{
    const float* x   = (const float*)d_in[0];
    const float* w0  = (const float*)d_in[1];
    const float* w1  = (const float*)d_in[2];
    const float* w2  = (const float*)d_in[3];
    const int*   sel = (const int*)d_in[4];
    const float* rw  = (const float*)d_in[5];
    float* out = (float*)d_out;

    cudaFuncSetAttribute(k_gemm1, cudaFuncAttributeMaxDynamicSharedMemorySize, SMEM_B);
    cudaFuncSetAttribute(k_gemm2, cudaFuncAttributeMaxDynamicSharedMemorySize, SMEM_B);

    k_init<<<1, 32>>>();
    k_hist<<<NPAIR / 256, 256>>>(sel);
    k_scan<<<1, 1>>>();
    k_fill<<<NPAIR / 256, 256>>>(sel);

    dim3 g1(I_DIM / 64, 32, E_NUM);      // (22, 32, 16)
    k_gemm1<<<g1, 256, SMEM_B>>>(x, w0, w1);

    dim3 g2(D_DIM / 128, 32, E_NUM);     // (16, 32, 16)
    k_gemm2<<<g2, 256, SMEM_B>>>(w2, rw, out);
}

// round 10
// speedup vs baseline: 5.2909x; 1.1524x over previous
#include <cuda_runtime.h>
#include <cuda_fp16.h>
#include <math.h>
#include <stdint.h>

// Problem constants
#define T_TOK 4096
#define D_DIM 2048
#define E_NUM 16
#define I_DIM 1408
#define K_TOP 4
#define NPAIR (T_TOK * K_TOP)   // 16384

// -------- device scratch --------
__device__ int g_count[E_NUM];
__device__ int g_fill[E_NUM];
__device__ int g_offset[E_NUM + 1];
__device__ int g_pairs[NPAIR];
__device__ __half g_H[(size_t)NPAIR * I_DIM];   // ~46 MB fp16 intermediate

// ---------------- routing ----------------
__global__ void k_init() {
    int i = threadIdx.x;
    if (i < E_NUM) { g_count[i] = 0; g_fill[i] = 0; }
}
__global__ void k_hist(const int* __restrict__ sel) {
    int p = blockIdx.x * blockDim.x + threadIdx.x;
    if (p < NPAIR) atomicAdd(&g_count[sel[p]], 1);
}
__global__ void k_scan() {
    int acc = 0;
    for (int e = 0; e < E_NUM; e++) { g_offset[e] = acc; acc += g_count[e]; }
    g_offset[E_NUM] = acc;
}
__global__ void k_fill(const int* __restrict__ sel) {
    int p = blockIdx.x * blockDim.x + threadIdx.x;
    if (p < NPAIR) {
        int e = sel[p];
        int pos = g_offset[e] + atomicAdd(&g_fill[e], 1);
        g_pairs[pos] = p;
    }
}

// ---------------- helpers ----------------
// pack two f32 -> f16x2 (lo = first arg in memory order)
__device__ __forceinline__ uint32_t pk(float lo, float hi) {
    uint32_t u;
    asm("cvt.rn.f16x2.f32 %0, %1, %2;" : "=r"(u) : "f"(hi), "f"(lo));
    return u;
}
__device__ __forceinline__ void mma16(float* d, const uint32_t* a, const uint32_t* b) {
    asm volatile(
        "mma.sync.aligned.m16n8k16.row.col.f32.f16.f16.f32 "
        "{%0,%1,%2,%3}, {%4,%5,%6,%7}, {%8,%9}, {%0,%1,%2,%3};"
        : "+f"(d[0]), "+f"(d[1]), "+f"(d[2]), "+f"(d[3])
        : "r"(a[0]), "r"(a[1]), "r"(a[2]), "r"(a[3]), "r"(b[0]), "r"(b[1]));
}

// ---------------- tiling ----------------
#define BM   128
#define BK   32                        // K elements per chunk (2 x k16 steps)
#define RS   20                        // smem row stride in b32 (16 data words + 4 pad)
#define ROWSM 128                      // rows per smem matrix (A and B both 128)
#define STAGE_U (2 * ROWSM * RS)       // b32 per stage (A+B) = 5120

// =====================================================================
// GEMM1: D0 = X@W0^T, D1 = X@W1^T (shared X), H = silu(D0)*D1  [fp16 MMA]
// Block: 128 rows x 64 I-cols (both matrices). B smem = [W0 64 rows | W1 64 rows].
// 8 warps: wr=wid&1 (m half), wc=wid>>1 (16-col group).
// =====================================================================
__global__ __launch_bounds__(256, 1)
void k_gemm1(const float* __restrict__ x,
             const float* __restrict__ w0,
             const float* __restrict__ w1)
{
    __shared__ uint32_t sm[2 * STAGE_U];
    __shared__ int rowTok[BM];

    int e   = blockIdx.z;
    int cnt = g_count[e];
    int m0  = blockIdx.y * BM;
    if (m0 >= cnt) return;
    int n0   = blockIdx.x * 64;
    int base = g_offset[e];

    int tid  = threadIdx.x;
    int wid  = tid >> 5;
    int lane = tid & 31;
    int g    = lane >> 2;
    int t    = lane & 3;
    int wr   = wid & 1;
    int wc   = wid >> 1;

    if (tid < BM) {
        int r = m0 + tid;
        rowTok[tid] = (r < cnt) ? (g_pairs[base + r] / K_TOP) : -1;
    }
    __syncthreads();

    const float* w0e = w0 + (size_t)e * I_DIM * D_DIM;
    const float* w1e = w1 + (size_t)e * I_DIM * D_DIM;

    // per-thread producer descriptors: 4 A-row-segments + 4 B-row-segments
    const float* pX[4];
    const float* pW[4];
    bool vX[4];
    int soff[4];
#pragma unroll
    for (int i = 0; i < 4; i++) {
        int idx = i * 256 + tid;
        int row = idx >> 3;        // 0..127
        int c4  = idx & 7;         // group of 4 floats
        soff[i] = row * RS + c4 * 2;   // b32 offset (4 halves = 2 b32)
        int tok = rowTok[row];
        vX[i] = (tok >= 0);
        pX[i] = x + (size_t)(vX[i] ? tok : 0) * D_DIM + c4 * 4;
        pW[i] = (row < 64)
              ? (w0e + (size_t)(n0 + row) * D_DIM + c4 * 4)
              : (w1e + (size_t)(n0 + row - 64) * D_DIM + c4 * 4);
    }

    float acc[4][4][4];
#pragma unroll
    for (int mi = 0; mi < 4; mi++)
#pragma unroll
        for (int ni = 0; ni < 4; ni++)
#pragma unroll
            for (int q = 0; q < 4; q++) acc[mi][ni][q] = 0.f;

    const int nbase[4] = {16 * wc, 16 * wc + 8, 64 + 16 * wc, 64 + 16 * wc + 8};

    float4 rx[4], rv[4];
#pragma unroll
    for (int i = 0; i < 4; i++) {
        rx[i] = vX[i] ? *(const float4*)pX[i] : make_float4(0, 0, 0, 0);
        rv[i] = *(const float4*)pW[i];
    }
    {
        uint32_t* Ad = sm;
        uint32_t* Bd = sm + ROWSM * RS;
#pragma unroll
        for (int i = 0; i < 4; i++) {
            *(uint2*)(Ad + soff[i]) = make_uint2(pk(rx[i].x, rx[i].y), pk(rx[i].z, rx[i].w));
            *(uint2*)(Bd + soff[i]) = make_uint2(pk(rv[i].x, rv[i].y), pk(rv[i].z, rv[i].w));
        }
    }
    __syncthreads();

    const int NCHUNK = D_DIM / BK;  // 64
    for (int c = 0; c < NCHUNK; c++) {
        int cur = c & 1;
        if (c + 1 < NCHUNK) {
            int ko = (c + 1) * BK;
#pragma unroll
            for (int i = 0; i < 4; i++) {
                rx[i] = vX[i] ? *(const float4*)(pX[i] + ko) : make_float4(0, 0, 0, 0);
                rv[i] = *(const float4*)(pW[i] + ko);
            }
        }
        const uint32_t* As = sm + cur * STAGE_U;
        const uint32_t* Bs = As + ROWSM * RS;
#pragma unroll
        for (int s = 0; s < 2; s++) {       // two k16 steps per chunk
            int kk = s * 8;                 // b32 offset within row
            uint32_t a[4][4], b[4][2];
#pragma unroll
            for (int mi = 0; mi < 4; mi++) {
                int r = (wr * 64 + mi * 16 + g) * RS + kk + t;
                a[mi][0] = As[r];
                a[mi][1] = As[r + 8 * RS];
                a[mi][2] = As[r + 4];
                a[mi][3] = As[r + 8 * RS + 4];
            }
#pragma unroll
            for (int ni = 0; ni < 4; ni++) {
                int r = (nbase[ni] + g) * RS + kk + t;
                b[ni][0] = Bs[r];
                b[ni][1] = Bs[r + 4];
            }
#pragma unroll
            for (int mi = 0; mi < 4; mi++)
#pragma unroll
                for (int ni = 0; ni < 4; ni++)
                    mma16(acc[mi][ni], a[mi], b[ni]);
        }
        if (c + 1 < NCHUNK) {
            uint32_t* Ad = sm + (cur ^ 1) * STAGE_U;
            uint32_t* Bd = Ad + ROWSM * RS;
#pragma unroll
            for (int i = 0; i < 4; i++) {
                *(uint2*)(Ad + soff[i]) = make_uint2(pk(rx[i].x, rx[i].y), pk(rx[i].z, rx[i].w));
                *(uint2*)(Bd + soff[i]) = make_uint2(pk(rv[i].x, rv[i].y), pk(rv[i].z, rv[i].w));
            }
        }
        __syncthreads();
    }

    // epilogue: H = silu(D0) * D1, store fp16 (pairs: ni and ni+2)
#pragma unroll
    for (int mi = 0; mi < 4; mi++) {
#pragma unroll
        for (int jj = 0; jj < 2; jj++) {
            int col = n0 + 16 * wc + 8 * jj + 2 * t;
            float* d0 = acc[mi][jj];
            float* d1 = acc[mi][jj + 2];
            int r0 = wr * 64 + mi * 16 + g;
            if (m0 + r0 < cnt) {
                float h0 = (d0[0] / (1.f + __expf(-d0[0]))) * d1[0];
                float h1 = (d0[1] / (1.f + __expf(-d0[1]))) * d1[1];
                *(uint32_t*)((__half*)g_H + (size_t)(base + m0 + r0) * I_DIM + col) = pk(h0, h1);
            }
            int r1 = r0 + 8;
            if (m0 + r1 < cnt) {
                float h0 = (d0[2] / (1.f + __expf(-d0[2]))) * d1[2];
                float h1 = (d0[3] / (1.f + __expf(-d0[3]))) * d1[3];
                *(uint32_t*)((__half*)g_H + (size_t)(base + m0 + r1) * I_DIM + col) = pk(h0, h1);
            }
        }
    }
}

// =====================================================================
// GEMM2: OUT[pair,:] = (H @ W2^T) * rw[pair].  Block 128x128, warp 64x32. [fp16]
// A (H) is already fp16 in gmem -> producer is a pure copy (2 x uint4 per
// thread per chunk = 16 halves, covering the full 128x32 tile).
// =====================================================================
__global__ __launch_bounds__(256, 1)
void k_gemm2(const float* __restrict__ w2,
             const float* __restrict__ rw,
             float* __restrict__ out)
{
    __shared__ uint32_t sm[2 * STAGE_U];
    __shared__ int rowPair[BM];

    int e   = blockIdx.z;
    int cnt = g_count[e];
    int m0  = blockIdx.y * BM;
    if (m0 >= cnt) return;
    int n0   = blockIdx.x * 128;
    int base = g_offset[e];

    int tid  = threadIdx.x;
    int wid  = tid >> 5;
    int lane = tid & 31;
    int g    = lane >> 2;
    int t    = lane & 3;
    int wr   = wid & 1;
    int wc   = wid >> 1;

    if (tid < BM) {
        int r = m0 + tid;
        rowPair[tid] = (r < cnt) ? g_pairs[base + r] : -1;
    }
    __syncthreads();

    const float* w2e = w2 + (size_t)e * D_DIM * I_DIM;

    // A producer: 16 halves (2 x uint4) per thread per chunk.
    // row = tid>>1 (0..127), half-group ac2 = tid&1 -> halves [ac2*16, ac2*16+16)
    int arow = tid >> 1;
    int ac2  = tid & 1;
    bool vH  = (m0 + arow < cnt);
    const __half* pH = (__half*)g_H + (size_t)(base + (vH ? (m0 + arow) : 0)) * I_DIM + ac2 * 16;
    int asoff = arow * RS + ac2 * 8;   // b32 offset: 16 halves = 8 words

    // B producer: 4 float4 per thread per chunk
    const float* pW[4];
    int soff[4];
#pragma unroll
    for (int i = 0; i < 4; i++) {
        int idx = i * 256 + tid;
        int row = idx >> 3;
        int c4  = idx & 7;
        soff[i] = row * RS + c4 * 2;
        pW[i] = w2e + (size_t)(n0 + row) * I_DIM + c4 * 4;
    }

    float acc[4][4][4];
#pragma unroll
    for (int mi = 0; mi < 4; mi++)
#pragma unroll
        for (int ni = 0; ni < 4; ni++)
#pragma unroll
            for (int q = 0; q < 4; q++) acc[mi][ni][q] = 0.f;

    uint4  rh0, rh1;
    float4 rv[4];
    rh0 = vH ? *(const uint4*)pH       : make_uint4(0, 0, 0, 0);
    rh1 = vH ? *(const uint4*)(pH + 8) : make_uint4(0, 0, 0, 0);
#pragma unroll
    for (int i = 0; i < 4; i++) rv[i] = *(const float4*)pW[i];
    {
        uint32_t* Ad = sm;
        uint32_t* Bd = sm + ROWSM * RS;
        *(uint4*)(Ad + asoff)     = rh0;
        *(uint4*)(Ad + asoff + 4) = rh1;
#pragma unroll
        for (int i = 0; i < 4; i++)
            *(uint2*)(Bd + soff[i]) = make_uint2(pk(rv[i].x, rv[i].y), pk(rv[i].z, rv[i].w));
    }
    __syncthreads();

    const int NCHUNK = I_DIM / BK;  // 44
    for (int c = 0; c < NCHUNK; c++) {
        int cur = c & 1;
        if (c + 1 < NCHUNK) {
            int ko = (c + 1) * BK;
            rh0 = vH ? *(const uint4*)(pH + ko)     : make_uint4(0, 0, 0, 0);
            rh1 = vH ? *(const uint4*)(pH + ko + 8) : make_uint4(0, 0, 0, 0);
#pragma unroll
            for (int i = 0; i < 4; i++) rv[i] = *(const float4*)(pW[i] + ko);
        }
        const uint32_t* As = sm + cur * STAGE_U;
        const uint32_t* Bs = As + ROWSM * RS;
#pragma unroll
        for (int s = 0; s < 2; s++) {
            int kk = s * 8;
            uint32_t a[4][4], b[4][2];
#pragma unroll
            for (int mi = 0; mi < 4; mi++) {
                int r = (wr * 64 + mi * 16 + g) * RS + kk + t;
                a[mi][0] = As[r];
                a[mi][1] = As[r + 8 * RS];
                a[mi][2] = As[r + 4];
                a[mi][3] = As[r + 8 * RS + 4];
            }
#pragma unroll
            for (int ni = 0; ni < 4; ni++) {
                int r = (32 * wc + 8 * ni + g) * RS + kk + t;
                b[ni][0] = Bs[r];
                b[ni][1] = Bs[r + 4];
            }
#pragma unroll
            for (int mi = 0; mi < 4; mi++)
#pragma unroll
                for (int ni = 0; ni < 4; ni++)
                    mma16(acc[mi][ni], a[mi], b[ni]);
        }
        if (c + 1 < NCHUNK) {
            uint32_t* Ad = sm + (cur ^ 1) * STAGE_U;
            uint32_t* Bd = Ad + ROWSM * RS;
            *(uint4*)(Ad + asoff)     = rh0;
            *(uint4*)(Ad + asoff + 4) = rh1;
#pragma unroll
            for (int i = 0; i < 4; i++)
                *(uint2*)(Bd + soff[i]) = make_uint2(pk(rv[i].x, rv[i].y), pk(rv[i].z, rv[i].w));
        }
        __syncthreads();
    }

    // epilogue: scale by routing weight, scatter to out[pair]
#pragma unroll
    for (int mi = 0; mi < 4; mi++) {
        int r0 = wr * 64 + mi * 16 + g;
#pragma unroll
        for (int half = 0; half < 2; half++) {
            int r = r0 + half * 8;
            if (m0 + r < cnt) {
                int pair = rowPair[r];
                float w  = rw[pair];
                float* op = out + (size_t)pair * D_DIM + n0;
#pragma unroll
                for (int ni = 0; ni < 4; ni++) {
                    int col = 32 * wc + 8 * ni + 2 * t;
                    float v0 = acc[mi][ni][half * 2 + 0] * w;
                    float v1 = acc[mi][ni][half * 2 + 1] * w;
                    *(float2*)(op + col) = make_float2(v0, v1);
                }
            }
        }
    }
}

// ---------------- launch ----------------
extern "C" void kernel_launch(void* const* d_in, const int* in_sizes, int n_in,
                              void* d_out, int out_size)
{
    const float* x   = (const float*)d_in[0];
    const float* w0  = (const float*)d_in[1];
    const float* w1  = (const float*)d_in[2];
    const float* w2  = (const float*)d_in[3];
    const int*   sel = (const int*)d_in[4];
    const float* rw  = (const float*)d_in[5];
    float* out = (float*)d_out;

    k_init<<<1, 32>>>();
    k_hist<<<NPAIR / 256, 256>>>(sel);
    k_scan<<<1, 1>>>();
    k_fill<<<NPAIR / 256, 256>>>(sel);

    dim3 g1(I_DIM / 64, 32, E_NUM);      // (22, 32, 16)
    k_gemm1<<<g1, 256>>>(x, w0, w1);

    dim3 g2(D_DIM / 128, 32, E_NUM);     // (16, 32, 16)
    k_gemm2<<<g2, 256>>>(w2, rw, out);
}

// round 11
// speedup vs baseline: 7.1617x; 1.3536x over previous
#include <cuda_runtime.h>
#include <cuda_fp16.h>
#include <math.h>
#include <stdint.h>

// Problem constants
#define T_TOK 4096
#define D_DIM 2048
#define E_NUM 16
#define I_DIM 1408
#define K_TOP 4
#define NPAIR (T_TOK * K_TOP)   // 16384
#define WELEM (E_NUM * I_DIM * D_DIM)   // 46,137,344 per weight tensor

// -------- device scratch --------
__device__ int g_count[E_NUM];
__device__ int g_fill[E_NUM];
__device__ int g_offset[E_NUM + 1];
__device__ int g_pairs[NPAIR];
__device__ __half g_H[(size_t)NPAIR * I_DIM];     // 46 MB fp16 intermediate
__device__ __half g_W0h[WELEM];                   // 92 MB
__device__ __half g_W1h[WELEM];                   // 92 MB
__device__ __half g_W2h[WELEM];                   // 92 MB
__device__ __half g_Xh[(size_t)T_TOK * D_DIM];    // 16 MB

// ---------------- routing ----------------
__global__ void k_init() {
    int i = threadIdx.x;
    if (i < E_NUM) { g_count[i] = 0; g_fill[i] = 0; }
}
__global__ void k_hist(const int* __restrict__ sel) {
    int p = blockIdx.x * blockDim.x + threadIdx.x;
    if (p < NPAIR) atomicAdd(&g_count[sel[p]], 1);
}
__global__ void k_scan() {
    int acc = 0;
    for (int e = 0; e < E_NUM; e++) { g_offset[e] = acc; acc += g_count[e]; }
    g_offset[E_NUM] = acc;
}
__global__ void k_fill(const int* __restrict__ sel) {
    int p = blockIdx.x * blockDim.x + threadIdx.x;
    if (p < NPAIR) {
        int e = sel[p];
        int pos = g_offset[e] + atomicAdd(&g_fill[e], 1);
        g_pairs[pos] = p;
    }
}

// ---------------- helpers ----------------
// pack two f32 -> f16x2 (lo = first arg in memory order)
__device__ __forceinline__ uint32_t pk(float lo, float hi) {
    uint32_t u;
    asm("cvt.rn.f16x2.f32 %0, %1, %2;" : "=r"(u) : "f"(hi), "f"(lo));
    return u;
}
__device__ __forceinline__ void mma16(float* d, const uint32_t* a, const uint32_t* b) {
    asm volatile(
        "mma.sync.aligned.m16n8k16.row.col.f32.f16.f16.f32 "
        "{%0,%1,%2,%3}, {%4,%5,%6,%7}, {%8,%9}, {%0,%1,%2,%3};"
        : "+f"(d[0]), "+f"(d[1]), "+f"(d[2]), "+f"(d[3])
        : "r"(a[0]), "r"(a[1]), "r"(a[2]), "r"(a[3]), "r"(b[0]), "r"(b[1]));
}

// fp32 -> fp16 bulk conversion (4 floats / thread)
__global__ __launch_bounds__(256) void k_cvt(const float* __restrict__ src,
                                             __half* __restrict__ dst, int n4) {
    int i = blockIdx.x * blockDim.x + threadIdx.x;
    if (i < n4) {
        float4 v = ((const float4*)src)[i];
        ((uint2*)dst)[i] = make_uint2(pk(v.x, v.y), pk(v.z, v.w));
    }
}

// ---------------- tiling ----------------
#define BM   256
#define BK   32                         // K halves per chunk (2 x k16 steps)
#define RS   20                         // smem row stride in b32 (16 data + 4 pad)
#define AU   (256 * RS)                 // A region b32 per stage
#define BU   (128 * RS)                 // B region b32 per stage
#define STAGE_U (AU + BU)               // 7680 b32 = 30 KB
#define SMEM_B  (2 * STAGE_U * 4)       // 61440 bytes dynamic

// =====================================================================
// GEMM1: D0 = X@W0^T, D1 = X@W1^T (shared X), H = silu(D0)*D1  [fp16]
// Block: 256 rows x 64 I-cols. B smem = [W0h 64 rows | W1h 64 rows].
// 16 warps: wr=wid&3 (64-row quarter), wc=wid>>2 (16-col group).
// All producers are pure fp16 copies (pre-converted weights/X).
// =====================================================================
__global__ __launch_bounds__(512, 1)
void k_gemm1()
{
    extern __shared__ uint32_t sm[];
    __shared__ int rowTok[BM];

    int e   = blockIdx.z;
    int cnt = g_count[e];
    int m0  = blockIdx.y * BM;
    if (m0 >= cnt) return;
    int n0   = blockIdx.x * 64;
    int base = g_offset[e];

    int tid  = threadIdx.x;
    int wid  = tid >> 5;
    int lane = tid & 31;
    int g    = lane >> 2;
    int t    = lane & 3;
    int wr   = wid & 3;
    int wc   = wid >> 2;

    if (tid < BM) {
        int r = m0 + tid;
        rowTok[tid] = (r < cnt) ? (g_pairs[base + r] / K_TOP) : -1;
    }
    __syncthreads();

    // A producer: 16 halves (2 uint4) / thread / chunk
    int arow = tid >> 1;
    int ac2  = tid & 1;
    int tok  = rowTok[arow];
    bool vA  = (tok >= 0);
    const __half* pA = g_Xh + (size_t)(vA ? tok : 0) * D_DIM + ac2 * 16;
    int asoff = arow * RS + ac2 * 8;

    // B producer: 8 halves (1 uint4) / thread / chunk
    int brow = tid >> 2;
    int bc   = tid & 3;
    const __half* pB = (brow < 64)
        ? (g_W0h + (size_t)(e * I_DIM + n0 + brow) * D_DIM + bc * 8)
        : (g_W1h + (size_t)(e * I_DIM + n0 + brow - 64) * D_DIM + bc * 8);
    int bsoff = brow * RS + bc * 4;

    float acc[4][4][4];
#pragma unroll
    for (int mi = 0; mi < 4; mi++)
#pragma unroll
        for (int ni = 0; ni < 4; ni++)
#pragma unroll
            for (int q = 0; q < 4; q++) acc[mi][ni][q] = 0.f;

    const int nbase[4] = {16 * wc, 16 * wc + 8, 64 + 16 * wc, 64 + 16 * wc + 8};

    uint4 ra0, ra1, rb;
    ra0 = vA ? *(const uint4*)pA       : make_uint4(0, 0, 0, 0);
    ra1 = vA ? *(const uint4*)(pA + 8) : make_uint4(0, 0, 0, 0);
    rb  = *(const uint4*)pB;
    {
        uint32_t* Ad = sm;
        uint32_t* Bd = sm + AU;
        *(uint4*)(Ad + asoff)     = ra0;
        *(uint4*)(Ad + asoff + 4) = ra1;
        *(uint4*)(Bd + bsoff)     = rb;
    }
    __syncthreads();

    const int NCHUNK = D_DIM / BK;  // 64
    for (int c = 0; c < NCHUNK; c++) {
        int cur = c & 1;
        if (c + 1 < NCHUNK) {
            int ko = (c + 1) * BK;
            ra0 = vA ? *(const uint4*)(pA + ko)     : make_uint4(0, 0, 0, 0);
            ra1 = vA ? *(const uint4*)(pA + ko + 8) : make_uint4(0, 0, 0, 0);
            rb  = *(const uint4*)(pB + ko);
        }
        const uint32_t* As = sm + cur * STAGE_U;
        const uint32_t* Bs = As + AU;
#pragma unroll
        for (int s = 0; s < 2; s++) {       // two k16 steps per chunk
            int kk = s * 8;
            uint32_t a[4][4], b[4][2];
#pragma unroll
            for (int mi = 0; mi < 4; mi++) {
                int r = (wr * 64 + mi * 16 + g) * RS + kk + t;
                a[mi][0] = As[r];
                a[mi][1] = As[r + 8 * RS];
                a[mi][2] = As[r + 4];
                a[mi][3] = As[r + 8 * RS + 4];
            }
#pragma unroll
            for (int ni = 0; ni < 4; ni++) {
                int r = (nbase[ni] + g) * RS + kk + t;
                b[ni][0] = Bs[r];
                b[ni][1] = Bs[r + 4];
            }
#pragma unroll
            for (int mi = 0; mi < 4; mi++)
#pragma unroll
                for (int ni = 0; ni < 4; ni++)
                    mma16(acc[mi][ni], a[mi], b[ni]);
        }
        if (c + 1 < NCHUNK) {
            uint32_t* Ad = sm + (cur ^ 1) * STAGE_U;
            uint32_t* Bd = Ad + AU;
            *(uint4*)(Ad + asoff)     = ra0;
            *(uint4*)(Ad + asoff + 4) = ra1;
            *(uint4*)(Bd + bsoff)     = rb;
        }
        __syncthreads();
    }

    // epilogue: H = silu(D0) * D1, store fp16 (pairs: ni and ni+2)
#pragma unroll
    for (int mi = 0; mi < 4; mi++) {
#pragma unroll
        for (int jj = 0; jj < 2; jj++) {
            int col = n0 + 16 * wc + 8 * jj + 2 * t;
            float* d0 = acc[mi][jj];
            float* d1 = acc[mi][jj + 2];
            int r0 = wr * 64 + mi * 16 + g;
            if (m0 + r0 < cnt) {
                float h0 = (d0[0] / (1.f + __expf(-d0[0]))) * d1[0];
                float h1 = (d0[1] / (1.f + __expf(-d0[1]))) * d1[1];
                *(uint32_t*)((__half*)g_H + (size_t)(base + m0 + r0) * I_DIM + col) = pk(h0, h1);
            }
            int r1 = r0 + 8;
            if (m0 + r1 < cnt) {
                float h0 = (d0[2] / (1.f + __expf(-d0[2]))) * d1[2];
                float h1 = (d0[3] / (1.f + __expf(-d0[3]))) * d1[3];
                *(uint32_t*)((__half*)g_H + (size_t)(base + m0 + r1) * I_DIM + col) = pk(h0, h1);
            }
        }
    }
}

// =====================================================================
// GEMM2: OUT[pair,:] = (H @ W2^T) * rw[pair].  Block 256x128, warp 64x32.
// =====================================================================
__global__ __launch_bounds__(512, 1)
void k_gemm2(const float* __restrict__ rw,
             float* __restrict__ out)
{
    extern __shared__ uint32_t sm[];
    __shared__ int rowPair[BM];

    int e   = blockIdx.z;
    int cnt = g_count[e];
    int m0  = blockIdx.y * BM;
    if (m0 >= cnt) return;
    int n0   = blockIdx.x * 128;
    int base = g_offset[e];

    int tid  = threadIdx.x;
    int wid  = tid >> 5;
    int lane = tid & 31;
    int g    = lane >> 2;
    int t    = lane & 3;
    int wr   = wid & 3;
    int wc   = wid >> 2;

    if (tid < BM) {
        int r = m0 + tid;
        rowPair[tid] = (r < cnt) ? g_pairs[base + r] : -1;
    }
    __syncthreads();

    // A producer: 16 halves (2 uint4) / thread / chunk from g_H
    int arow = tid >> 1;
    int ac2  = tid & 1;
    bool vA  = (m0 + arow < cnt);
    const __half* pA = (__half*)g_H + (size_t)(base + (vA ? (m0 + arow) : 0)) * I_DIM + ac2 * 16;
    int asoff = arow * RS + ac2 * 8;

    // B producer: 8 halves (1 uint4) / thread / chunk from W2h
    int brow = tid >> 2;
    int bc   = tid & 3;
    const __half* pB = g_W2h + (size_t)(e * D_DIM + n0 + brow) * I_DIM + bc * 8;
    int bsoff = brow * RS + bc * 4;

    float acc[4][4][4];
#pragma unroll
    for (int mi = 0; mi < 4; mi++)
#pragma unroll
        for (int ni = 0; ni < 4; ni++)
#pragma unroll
            for (int q = 0; q < 4; q++) acc[mi][ni][q] = 0.f;

    uint4 ra0, ra1, rb;
    ra0 = vA ? *(const uint4*)pA       : make_uint4(0, 0, 0, 0);
    ra1 = vA ? *(const uint4*)(pA + 8) : make_uint4(0, 0, 0, 0);
    rb  = *(const uint4*)pB;
    {
        uint32_t* Ad = sm;
        uint32_t* Bd = sm + AU;
        *(uint4*)(Ad + asoff)     = ra0;
        *(uint4*)(Ad + asoff + 4) = ra1;
        *(uint4*)(Bd + bsoff)     = rb;
    }
    __syncthreads();

    const int NCHUNK = I_DIM / BK;  // 44
    for (int c = 0; c < NCHUNK; c++) {
        int cur = c & 1;
        if (c + 1 < NCHUNK) {
            int ko = (c + 1) * BK;
            ra0 = vA ? *(const uint4*)(pA + ko)     : make_uint4(0, 0, 0, 0);
            ra1 = vA ? *(const uint4*)(pA + ko + 8) : make_uint4(0, 0, 0, 0);
            rb  = *(const uint4*)(pB + ko);
        }
        const uint32_t* As = sm + cur * STAGE_U;
        const uint32_t* Bs = As + AU;
#pragma unroll
        for (int s = 0; s < 2; s++) {
            int kk = s * 8;
            uint32_t a[4][4], b[4][2];
#pragma unroll
            for (int mi = 0; mi < 4; mi++) {
                int r = (wr * 64 + mi * 16 + g) * RS + kk + t;
                a[mi][0] = As[r];
                a[mi][1] = As[r + 8 * RS];
                a[mi][2] = As[r + 4];
                a[mi][3] = As[r + 8 * RS + 4];
            }
#pragma unroll
            for (int ni = 0; ni < 4; ni++) {
                int r = (32 * wc + 8 * ni + g) * RS + kk + t;
                b[ni][0] = Bs[r];
                b[ni][1] = Bs[r + 4];
            }
#pragma unroll
            for (int mi = 0; mi < 4; mi++)
#pragma unroll
                for (int ni = 0; ni < 4; ni++)
                    mma16(acc[mi][ni], a[mi], b[ni]);
        }
        if (c + 1 < NCHUNK) {
            uint32_t* Ad = sm + (cur ^ 1) * STAGE_U;
            uint32_t* Bd = Ad + AU;
            *(uint4*)(Ad + asoff)     = ra0;
            *(uint4*)(Ad + asoff + 4) = ra1;
            *(uint4*)(Bd + bsoff)     = rb;
        }
        __syncthreads();
    }

    // epilogue: scale by routing weight, scatter to out[pair]
#pragma unroll
    for (int mi = 0; mi < 4; mi++) {
        int r0 = wr * 64 + mi * 16 + g;
#pragma unroll
        for (int half = 0; half < 2; half++) {
            int r = r0 + half * 8;
            if (m0 + r < cnt) {
                int pair = rowPair[r];
                float w  = rw[pair];
                float* op = out + (size_t)pair * D_DIM + n0;
#pragma unroll
                for (int ni = 0; ni < 4; ni++) {
                    int col = 32 * wc + 8 * ni + 2 * t;
                    float v0 = acc[mi][ni][half * 2 + 0] * w;
                    float v1 = acc[mi][ni][half * 2 + 1] * w;
                    *(float2*)(op + col) = make_float2(v0, v1);
                }
            }
        }
    }
}

// ---------------- launch ----------------
extern "C" void kernel_launch(void* const* d_in, const int* in_sizes, int n_in,
                              void* d_out, int out_size)
{
    const float* x   = (const float*)d_in[0];
    const float* w0  = (const float*)d_in[1];
    const float* w1  = (const float*)d_in[2];
    const float* w2  = (const float*)d_in[3];
    const int*   sel = (const int*)d_in[4];
    const float* rw  = (const float*)d_in[5];
    float* out = (float*)d_out;

    cudaFuncSetAttribute(k_gemm1, cudaFuncAttributeMaxDynamicSharedMemorySize, SMEM_B);
    cudaFuncSetAttribute(k_gemm2, cudaFuncAttributeMaxDynamicSharedMemorySize, SMEM_B);

    k_init<<<1, 32>>>();
    k_hist<<<NPAIR / 256, 256>>>(sel);
    k_scan<<<1, 1>>>();
    k_fill<<<NPAIR / 256, 256>>>(sel);

    // fp32 -> fp16 pre-conversion (weights + activations)
    {
        __half *dW0h, *dW1h, *dW2h, *dXh;
        cudaGetSymbolAddress((void**)&dW0h, g_W0h);
        cudaGetSymbolAddress((void**)&dW1h, g_W1h);
        cudaGetSymbolAddress((void**)&dW2h, g_W2h);
        cudaGetSymbolAddress((void**)&dXh,  g_Xh);
        int w4 = WELEM / 4;                       // 11,534,336
        int x4 = (T_TOK * D_DIM) / 4;             // 2,097,152
        k_cvt<<<(w4 + 255) / 256, 256>>>(w0, dW0h, w4);
        k_cvt<<<(w4 + 255) / 256, 256>>>(w1, dW1h, w4);
        k_cvt<<<(w4 + 255) / 256, 256>>>(w2, dW2h, w4);
        k_cvt<<<(x4 + 255) / 256, 256>>>(x,  dXh,  x4);
    }

    dim3 g1(I_DIM / 64, T_TOK / BM, E_NUM);      // (22, 16, 16)
    k_gemm1<<<g1, 512, SMEM_B>>>();

    dim3 g2(D_DIM / 128, T_TOK / BM, E_NUM);     // (16, 16, 16)
    k_gemm2<<<g2, 512, SMEM_B>>>(rw, out);
}

// round 13
// speedup vs baseline: 8.5038x; 1.1874x over previous
#include <cuda_runtime.h>
#include <cuda_fp16.h>
#include <math.h>
#include <stdint.h>

// Problem constants
#define T_TOK 4096
#define D_DIM 2048
#define E_NUM 16
#define I_DIM 1408
#define K_TOP 4
#define NPAIR (T_TOK * K_TOP)   // 16384
#define WELEM (E_NUM * I_DIM * D_DIM)   // 46,137,344 per weight tensor

// -------- device scratch --------
__device__ int g_count[E_NUM];
__device__ int g_fill[E_NUM];
__device__ int g_offset[E_NUM + 1];
__device__ int g_pairs[NPAIR];
__device__ __half g_H[(size_t)NPAIR * I_DIM];     // 46 MB fp16 intermediate
__device__ __half g_W0h[WELEM];                   // 92 MB
__device__ __half g_W1h[WELEM];                   // 92 MB
__device__ __half g_W2h[WELEM];                   // 92 MB
__device__ __half g_Xh[(size_t)T_TOK * D_DIM];    // 16 MB

// ---------------- routing ----------------
__global__ void k_init() {
    int i = threadIdx.x;
    if (i < E_NUM) { g_count[i] = 0; g_fill[i] = 0; }
}
__global__ void k_hist(const int* __restrict__ sel) {
    int p = blockIdx.x * blockDim.x + threadIdx.x;
    if (p < NPAIR) atomicAdd(&g_count[sel[p]], 1);
}
__global__ void k_scan() {
    int acc = 0;
    for (int e = 0; e < E_NUM; e++) { g_offset[e] = acc; acc += g_count[e]; }
    g_offset[E_NUM] = acc;
}
__global__ void k_fill(const int* __restrict__ sel) {
    int p = blockIdx.x * blockDim.x + threadIdx.x;
    if (p < NPAIR) {
        int e = sel[p];
        int pos = g_offset[e] + atomicAdd(&g_fill[e], 1);
        g_pairs[pos] = p;
    }
}

// ---------------- helpers ----------------
__device__ __forceinline__ uint32_t pk(float lo, float hi) {
    uint32_t u;
    asm("cvt.rn.f16x2.f32 %0, %1, %2;" : "=r"(u) : "f"(hi), "f"(lo));
    return u;
}
__device__ __forceinline__ void mma16(float* d, const uint32_t* a, const uint32_t* b) {
    asm volatile(
        "mma.sync.aligned.m16n8k16.row.col.f32.f16.f16.f32 "
        "{%0,%1,%2,%3}, {%4,%5,%6,%7}, {%8,%9}, {%0,%1,%2,%3};"
        : "+f"(d[0]), "+f"(d[1]), "+f"(d[2]), "+f"(d[3])
        : "r"(a[0]), "r"(a[1]), "r"(a[2]), "r"(a[3]), "r"(b[0]), "r"(b[1]));
}
__device__ __forceinline__ void ldsm4(uint32_t& r0, uint32_t& r1, uint32_t& r2, uint32_t& r3,
                                      uint32_t saddr) {
    asm volatile("ldmatrix.sync.aligned.m8n8.x4.shared.b16 {%0,%1,%2,%3}, [%4];"
                 : "=r"(r0), "=r"(r1), "=r"(r2), "=r"(r3) : "r"(saddr));
}
__device__ __forceinline__ void cpa16(uint32_t saddr, const void* gaddr) {
    asm volatile("cp.async.cg.shared.global [%0], [%1], 16;" :: "r"(saddr), "l"(gaddr));
}
__device__ __forceinline__ void cp_commit() {
    asm volatile("cp.async.commit_group;" ::: "memory");
}
__device__ __forceinline__ void cp_wait2() {
    asm volatile("cp.async.wait_group 2;" ::: "memory");
}
__device__ __forceinline__ uint32_t smem_u32(const void* p) {
    uint32_t a;
    asm("{ .reg .u64 t; cvta.to.shared.u64 t, %1; cvt.u32.u64 %0, t; }" : "=r"(a) : "l"(p));
    return a;
}

// fp32 -> fp16 bulk conversion (4 floats / thread)
__global__ __launch_bounds__(256) void k_cvt(const float* __restrict__ src,
                                             __half* __restrict__ dst, int n4) {
    int i = blockIdx.x * blockDim.x + threadIdx.x;
    if (i < n4) {
        float4 v = ((const float4*)src)[i];
        ((uint2*)dst)[i] = make_uint2(pk(v.x, v.y), pk(v.z, v.w));
    }
}

// ---------------- tiling ----------------
#define BM   256
#define BK   32                         // K halves per chunk (2 x k16 steps)
#define RS   20                         // smem row stride in b32 (16 data + 4 pad)
#define AU   (256 * RS)                 // A region b32 per stage
#define BU   (128 * RS)                 // B region b32 per stage
#define STAGE_U (AU + BU)               // 7680 b32 = 30 KB
#define STAGES 4
#define SMEM_B  (STAGES * STAGE_U * 4)  // 122880 bytes dynamic

// =====================================================================
// GEMM1: D0 = X@W0^T, D1 = X@W1^T (shared X), H = silu(D0)*D1  [fp16]
// Block: 256 rows x 64 I-cols. B smem = [W0h 64 rows | W1h 64 rows].
// 16 warps: wr=wid&3 (64-row quarter), wc=wid>>2 (16-col group).
// cp.async 4-stage ring, ldmatrix fragment loads.
// =====================================================================
__global__ __launch_bounds__(512, 1)
void k_gemm1()
{
    extern __shared__ uint32_t sm[];
    __shared__ int rowTok[BM];

    int e   = blockIdx.z;
    int cnt = g_count[e];
    int m0  = blockIdx.y * BM;
    if (m0 >= cnt) return;
    int n0   = blockIdx.x * 64;
    int base = g_offset[e];

    int tid  = threadIdx.x;
    int wid  = tid >> 5;
    int lane = tid & 31;
    int g    = lane >> 2;
    int t    = lane & 3;
    int wr   = wid & 3;
    int wc   = wid >> 2;

    if (tid < BM) {
        int r = m0 + tid;
        rowTok[tid] = (r < cnt) ? (g_pairs[base + r] / K_TOP) : -1;
    }
    __syncthreads();

    uint32_t sbase = smem_u32(sm);

    // A producer: 16 halves (2 cp.async) / thread / chunk; clamp invalid rows to token 0
    int arow = tid >> 1;
    int ac2  = tid & 1;
    int tok  = rowTok[arow];
    const __half* pA = g_Xh + (size_t)(tok >= 0 ? tok : 0) * D_DIM + ac2 * 16;
    uint32_t adst = (uint32_t)(arow * RS + ac2 * 8) * 4;

    // B producer: 8 halves (1 cp.async) / thread / chunk
    int brow = tid >> 2;
    int bc   = tid & 3;
    const __half* pB = (brow < 64)
        ? (g_W0h + (size_t)(e * I_DIM + n0 + brow) * D_DIM + bc * 8)
        : (g_W1h + (size_t)(e * I_DIM + n0 + brow - 64) * D_DIM + bc * 8);
    uint32_t bdst = (uint32_t)(AU + brow * RS + bc * 4) * 4;

    // ldmatrix lane-address components
    int a_row_off = (lane & 7) + ((lane >> 3) & 1) * 8;
    int a_word    = ((lane >> 4) & 1) * 4;
    int b_row_off = (lane & 7) + ((lane >> 4) & 1) * 8;
    int b_word    = ((lane >> 3) & 1) * 4;
    uint32_t aAddr[4], bAddr[2];
#pragma unroll
    for (int mi = 0; mi < 4; mi++)
        aAddr[mi] = sbase + (uint32_t)((wr * 64 + mi * 16 + a_row_off) * RS + a_word) * 4;
    bAddr[0] = sbase + (uint32_t)(AU + (16 * wc + b_row_off) * RS + b_word) * 4;
    bAddr[1] = sbase + (uint32_t)(AU + (64 + 16 * wc + b_row_off) * RS + b_word) * 4;

    float acc[4][4][4];
#pragma unroll
    for (int mi = 0; mi < 4; mi++)
#pragma unroll
        for (int ni = 0; ni < 4; ni++)
#pragma unroll
            for (int q = 0; q < 4; q++) acc[mi][ni][q] = 0.f;

    const int NCHUNK = D_DIM / BK;  // 64

#define G1_ISSUE(stg, chk) do {                                   \
        uint32_t so = (uint32_t)(stg) * (STAGE_U * 4);            \
        const __half* s_ = pA + (chk) * BK;                       \
        cpa16(sbase + so + adst, s_);                             \
        cpa16(sbase + so + adst + 16, s_ + 8);                    \
        cpa16(sbase + so + bdst, pB + (chk) * BK);                \
    } while (0)

#pragma unroll
    for (int s = 0; s < 3; s++) { G1_ISSUE(s, s); cp_commit(); }

    for (int c = 0; c < NCHUNK; c++) {
        cp_wait2();
        __syncthreads();
        uint32_t so = (uint32_t)(c & 3) * (STAGE_U * 4);
#pragma unroll
        for (int s = 0; s < 2; s++) {
            uint32_t kb = s * 32;   // 8 words
            uint32_t a[4][4], b[4][2];
#pragma unroll
            for (int mi = 0; mi < 4; mi++)
                ldsm4(a[mi][0], a[mi][1], a[mi][2], a[mi][3], aAddr[mi] + so + kb);
            ldsm4(b[0][0], b[0][1], b[1][0], b[1][1], bAddr[0] + so + kb);
            ldsm4(b[2][0], b[2][1], b[3][0], b[3][1], bAddr[1] + so + kb);
#pragma unroll
            for (int mi = 0; mi < 4; mi++)
#pragma unroll
                for (int ni = 0; ni < 4; ni++)
                    mma16(acc[mi][ni], a[mi], b[ni]);
        }
        if (c + 3 < NCHUNK) G1_ISSUE((c + 3) & 3, c + 3);
        cp_commit();
    }

    // epilogue: H = silu(D0) * D1, store fp16 (pairs: ni and ni+2)
#pragma unroll
    for (int mi = 0; mi < 4; mi++) {
#pragma unroll
        for (int jj = 0; jj < 2; jj++) {
            int col = n0 + 16 * wc + 8 * jj + 2 * t;
            float* d0 = acc[mi][jj];
            float* d1 = acc[mi][jj + 2];
            int r0 = wr * 64 + mi * 16 + g;
            if (m0 + r0 < cnt) {
                float h0 = (d0[0] / (1.f + __expf(-d0[0]))) * d1[0];
                float h1 = (d0[1] / (1.f + __expf(-d0[1]))) * d1[1];
                *(uint32_t*)((__half*)g_H + (size_t)(base + m0 + r0) * I_DIM + col) = pk(h0, h1);
            }
            int r1 = r0 + 8;
            if (m0 + r1 < cnt) {
                float h0 = (d0[2] / (1.f + __expf(-d0[2]))) * d1[2];
                float h1 = (d0[3] / (1.f + __expf(-d0[3]))) * d1[3];
                *(uint32_t*)((__half*)g_H + (size_t)(base + m0 + r1) * I_DIM + col) = pk(h0, h1);
            }
        }
    }
}

// =====================================================================
// GEMM2: OUT[pair,:] = (H @ W2^T) * rw[pair].  Block 256x128, warp 64x32.
// =====================================================================
__global__ __launch_bounds__(512, 1)
void k_gemm2(const float* __restrict__ rw,
             float* __restrict__ out)
{
    extern __shared__ uint32_t sm[];
    __shared__ int rowPair[BM];

    int e   = blockIdx.z;
    int cnt = g_count[e];
    int m0  = blockIdx.y * BM;
    if (m0 >= cnt) return;
    int n0   = blockIdx.x * 128;
    int base = g_offset[e];

    int tid  = threadIdx.x;
    int wid  = tid >> 5;
    int lane = tid & 31;
    int g    = lane >> 2;
    int t    = lane & 3;
    int wr   = wid & 3;
    int wc   = wid >> 2;

    if (tid < BM) {
        int r = m0 + tid;
        rowPair[tid] = (r < cnt) ? g_pairs[base + r] : -1;
    }
    __syncthreads();

    uint32_t sbase = smem_u32(sm);

    // A producer from g_H (clamp invalid rows to first row of this tile)
    int arow = tid >> 1;
    int ac2  = tid & 1;
    int grow = (m0 + arow < cnt) ? (m0 + arow) : m0;
    const __half* pA = (__half*)g_H + (size_t)(base + grow) * I_DIM + ac2 * 16;
    uint32_t adst = (uint32_t)(arow * RS + ac2 * 8) * 4;

    // B producer from W2h
    int brow = tid >> 2;
    int bc   = tid & 3;
    const __half* pB = g_W2h + (size_t)(e * D_DIM + n0 + brow) * I_DIM + bc * 8;
    uint32_t bdst = (uint32_t)(AU + brow * RS + bc * 4) * 4;

    int a_row_off = (lane & 7) + ((lane >> 3) & 1) * 8;
    int a_word    = ((lane >> 4) & 1) * 4;
    int b_row_off = (lane & 7) + ((lane >> 4) & 1) * 8;
    int b_word    = ((lane >> 3) & 1) * 4;
    uint32_t aAddr[4], bAddr[2];
#pragma unroll
    for (int mi = 0; mi < 4; mi++)
        aAddr[mi] = sbase + (uint32_t)((wr * 64 + mi * 16 + a_row_off) * RS + a_word) * 4;
    bAddr[0] = sbase + (uint32_t)(AU + (32 * wc + b_row_off) * RS + b_word) * 4;
    bAddr[1] = sbase + (uint32_t)(AU + (32 * wc + 16 + b_row_off) * RS + b_word) * 4;

    float acc[4][4][4];
#pragma unroll
    for (int mi = 0; mi < 4; mi++)
#pragma unroll
        for (int ni = 0; ni < 4; ni++)
#pragma unroll
            for (int q = 0; q < 4; q++) acc[mi][ni][q] = 0.f;

    const int NCHUNK = I_DIM / BK;  // 44

#define G2_ISSUE(stg, chk) do {                                   \
        uint32_t so = (uint32_t)(stg) * (STAGE_U * 4);            \
        const __half* s_ = pA + (chk) * BK;                       \
        cpa16(sbase + so + adst, s_);                             \
        cpa16(sbase + so + adst + 16, s_ + 8);                    \
        cpa16(sbase + so + bdst, pB + (chk) * BK);                \
    } while (0)

#pragma unroll
    for (int s = 0; s < 3; s++) { G2_ISSUE(s, s); cp_commit(); }

    for (int c = 0; c < NCHUNK; c++) {
        cp_wait2();
        __syncthreads();
        uint32_t so = (uint32_t)(c & 3) * (STAGE_U * 4);
#pragma unroll
        for (int s = 0; s < 2; s++) {
            uint32_t kb = s * 32;
            uint32_t a[4][4], b[4][2];
#pragma unroll
            for (int mi = 0; mi < 4; mi++)
                ldsm4(a[mi][0], a[mi][1], a[mi][2], a[mi][3], aAddr[mi] + so + kb);
            ldsm4(b[0][0], b[0][1], b[1][0], b[1][1], bAddr[0] + so + kb);
            ldsm4(b[2][0], b[2][1], b[3][0], b[3][1], bAddr[1] + so + kb);
#pragma unroll
            for (int mi = 0; mi < 4; mi++)
#pragma unroll
                for (int ni = 0; ni < 4; ni++)
                    mma16(acc[mi][ni], a[mi], b[ni]);
        }
        if (c + 3 < NCHUNK) G2_ISSUE((c + 3) & 3, c + 3);
        cp_commit();
    }

    // epilogue: scale by routing weight, scatter to out[pair]
#pragma unroll
    for (int mi = 0; mi < 4; mi++) {
        int r0 = wr * 64 + mi * 16 + g;
#pragma unroll
        for (int half = 0; half < 2; half++) {
            int r = r0 + half * 8;
            if (m0 + r < cnt) {
                int pair = rowPair[r];
                float w  = rw[pair];
                float* op = out + (size_t)pair * D_DIM + n0;
#pragma unroll
                for (int ni = 0; ni < 4; ni++) {
                    int col = 32 * wc + 8 * ni + 2 * t;
                    float v0 = acc[mi][ni][half * 2 + 0] * w;
                    float v1 = acc[mi][ni][half * 2 + 1] * w;
                    *(float2*)(op + col) = make_float2(v0, v1);
                }
            }
        }
    }
}

// ---------------- launch ----------------
extern "C" void kernel_launch(void* const* d_in, const int* in_sizes, int n_in,
                              void* d_out, int out_size)
{
    const float* x   = (const float*)d_in[0];
    const float* w0  = (const float*)d_in[1];
    const float* w1  = (const float*)d_in[2];
    const float* w2  = (const float*)d_in[3];
    const int*   sel = (const int*)d_in[4];
    const float* rw  = (const float*)d_in[5];
    float* out = (float*)d_out;

    cudaFuncSetAttribute(k_gemm1, cudaFuncAttributeMaxDynamicSharedMemorySize, SMEM_B);
    cudaFuncSetAttribute(k_gemm2, cudaFuncAttributeMaxDynamicSharedMemorySize, SMEM_B);

    k_init<<<1, 32>>>();
    k_hist<<<NPAIR / 256, 256>>>(sel);
    k_scan<<<1, 1>>>();
    k_fill<<<NPAIR / 256, 256>>>(sel);

    // fp32 -> fp16 pre-conversion (weights + activations)
    {
        __half *dW0h, *dW1h, *dW2h, *dXh;
        cudaGetSymbolAddress((void**)&dW0h, g_W0h);
        cudaGetSymbolAddress((void**)&dW1h, g_W1h);
        cudaGetSymbolAddress((void**)&dW2h, g_W2h);
        cudaGetSymbolAddress((void**)&dXh,  g_Xh);
        int w4 = WELEM / 4;
        int x4 = (T_TOK * D_DIM) / 4;
        k_cvt<<<(w4 + 255) / 256, 256>>>(w0, dW0h, w4);
        k_cvt<<<(w4 + 255) / 256, 256>>>(w1, dW1h, w4);
        k_cvt<<<(w4 + 255) / 256, 256>>>(w2, dW2h, w4);
        k_cvt<<<(x4 + 255) / 256, 256>>>(x,  dXh,  x4);
    }

    dim3 g1(I_DIM / 64, T_TOK / BM, E_NUM);      // (22, 16, 16)
    k_gemm1<<<g1, 512, SMEM_B>>>();

    dim3 g2(D_DIM / 128, T_TOK / BM, E_NUM);     // (16, 16, 16)
    k_gemm2<<<g2, 512, SMEM_B>>>(rw, out);
}

// round 14
// speedup vs baseline: 9.3651x; 1.1013x over previous
#include <cuda_runtime.h>
#include <cuda_fp16.h>
#include <math.h>
#include <stdint.h>

// Problem constants
#define T_TOK 4096
#define D_DIM 2048
#define E_NUM 16
#define I_DIM 1408
#define K_TOP 4
#define NPAIR (T_TOK * K_TOP)   // 16384
#define WELEM (E_NUM * I_DIM * D_DIM)   // 46,137,344 per weight tensor

// -------- device scratch --------
__device__ int g_count[E_NUM];
__device__ int g_fill[E_NUM];
__device__ int g_offset[E_NUM + 1];
__device__ int g_pairs[NPAIR];
__device__ __half g_H[(size_t)NPAIR * I_DIM];     // 46 MB fp16 intermediate
__device__ __half g_W0h[WELEM];                   // 92 MB
__device__ __half g_W1h[WELEM];                   // 92 MB
__device__ __half g_W2h[WELEM];                   // 92 MB
__device__ __half g_Xh[(size_t)T_TOK * D_DIM];    // 16 MB

// ---------------- routing ----------------
__global__ void k_init() {
    int i = threadIdx.x;
    if (i < E_NUM) { g_count[i] = 0; g_fill[i] = 0; }
}
__global__ void k_hist(const int* __restrict__ sel) {
    int p = blockIdx.x * blockDim.x + threadIdx.x;
    if (p < NPAIR) atomicAdd(&g_count[sel[p]], 1);
}
__global__ void k_scan() {
    int acc = 0;
    for (int e = 0; e < E_NUM; e++) { g_offset[e] = acc; acc += g_count[e]; }
    g_offset[E_NUM] = acc;
}
__global__ void k_fill(const int* __restrict__ sel) {
    int p = blockIdx.x * blockDim.x + threadIdx.x;
    if (p < NPAIR) {
        int e = sel[p];
        int pos = g_offset[e] + atomicAdd(&g_fill[e], 1);
        g_pairs[pos] = p;
    }
}

// ---------------- helpers ----------------
__device__ __forceinline__ uint32_t pk(float lo, float hi) {
    uint32_t u;
    asm("cvt.rn.f16x2.f32 %0, %1, %2;" : "=r"(u) : "f"(hi), "f"(lo));
    return u;
}
__device__ __forceinline__ void mma16(float* d, const uint32_t* a, const uint32_t* b) {
    asm volatile(
        "mma.sync.aligned.m16n8k16.row.col.f32.f16.f16.f32 "
        "{%0,%1,%2,%3}, {%4,%5,%6,%7}, {%8,%9}, {%0,%1,%2,%3};"
        : "+f"(d[0]), "+f"(d[1]), "+f"(d[2]), "+f"(d[3])
        : "r"(a[0]), "r"(a[1]), "r"(a[2]), "r"(a[3]), "r"(b[0]), "r"(b[1]));
}
__device__ __forceinline__ void ldsm4(uint32_t& r0, uint32_t& r1, uint32_t& r2, uint32_t& r3,
                                      uint32_t saddr) {
    asm volatile("ldmatrix.sync.aligned.m8n8.x4.shared.b16 {%0,%1,%2,%3}, [%4];"
                 : "=r"(r0), "=r"(r1), "=r"(r2), "=r"(r3) : "r"(saddr));
}
__device__ __forceinline__ void cpa16(uint32_t saddr, const void* gaddr) {
    asm volatile("cp.async.cg.shared.global [%0], [%1], 16;" :: "r"(saddr), "l"(gaddr));
}
__device__ __forceinline__ void cp_commit() {
    asm volatile("cp.async.commit_group;" ::: "memory");
}
__device__ __forceinline__ void cp_wait1() {
    asm volatile("cp.async.wait_group 1;" ::: "memory");
}
__device__ __forceinline__ uint32_t smem_u32(const void* p) {
    uint32_t a;
    asm("{ .reg .u64 t; cvta.to.shared.u64 t, %1; cvt.u32.u64 %0, t; }" : "=r"(a) : "l"(p));
    return a;
}

// fused fp32 -> fp16 conversion of W0, W1, W2, X in one launch
#define W4 (WELEM / 4)                      // 11,534,336 float4 groups
#define X4 ((T_TOK * D_DIM) / 4)            // 2,097,152
__global__ __launch_bounds__(256) void k_cvt_all(
    const float* __restrict__ w0, const float* __restrict__ w1,
    const float* __restrict__ w2, const float* __restrict__ x,
    __half* __restrict__ dw0, __half* __restrict__ dw1,
    __half* __restrict__ dw2, __half* __restrict__ dx)
{
    int i = blockIdx.x * blockDim.x + threadIdx.x;
    const float* s; __half* d; int j;
    if (i < W4)            { s = w0; d = dw0; j = i; }
    else if (i < 2 * W4)   { s = w1; d = dw1; j = i - W4; }
    else if (i < 3 * W4)   { s = w2; d = dw2; j = i - 2 * W4; }
    else if (i < 3 * W4 + X4) { s = x; d = dx; j = i - 3 * W4; }
    else return;
    float4 v = ((const float4*)s)[j];
    ((uint2*)d)[j] = make_uint2(pk(v.x, v.y), pk(v.z, v.w));
}

// ---------------- tiling ----------------
#define BM   256
#define BK   64                         // K halves per chunk (4 x k16 steps) = 128B/row
#define RS   36                         // smem row stride in b32 (32 data + 4 pad)
#define AU   (256 * RS)                 // A region b32 per stage = 9216
#define BU   (128 * RS)                 // B region b32 per stage = 4608
#define STAGE_U (AU + BU)               // 13824 b32 = 54 KB
#define STAGES 3
#define SMEM_B  (STAGES * STAGE_U * 4)  // 165,888 bytes dynamic

// =====================================================================
// GEMM1: D0 = X@W0^T, D1 = X@W1^T (shared X), H = silu(D0)*D1  [fp16]
// Block: 256 rows x 64 I-cols. B smem = [W0h 64 rows | W1h 64 rows].
// 16 warps: wr=wid&3 (64-row quarter), wc=wid>>2 (16-col group).
// BK=64, 3-stage cp.async ring (wait_group 1), ldmatrix fragments.
// =====================================================================
__global__ __launch_bounds__(512, 1)
void k_gemm1()
{
    extern __shared__ uint32_t sm[];
    __shared__ int rowTok[BM];

    int e   = blockIdx.z;
    int cnt = g_count[e];
    int m0  = blockIdx.y * BM;
    if (m0 >= cnt) return;
    int n0   = blockIdx.x * 64;
    int base = g_offset[e];

    int tid  = threadIdx.x;
    int wid  = tid >> 5;
    int lane = tid & 31;
    int g    = lane >> 2;
    int t    = lane & 3;
    int wr   = wid & 3;
    int wc   = wid >> 2;

    if (tid < BM) {
        int r = m0 + tid;
        rowTok[tid] = (r < cnt) ? (g_pairs[base + r] / K_TOP) : -1;
    }
    __syncthreads();

    uint32_t sbase = smem_u32(sm);

    // A producer: 4 x 16B segs / thread / chunk (256 rows x 128B)
    uint32_t aoff[4], adst[4];
#pragma unroll
    for (int i = 0; i < 4; i++) {
        int seg = i * 512 + tid;
        int row = seg >> 3, c8 = seg & 7;
        int tok = rowTok[row];
        if (tok < 0) tok = 0;
        aoff[i] = (uint32_t)tok * D_DIM + c8 * 8;             // halves
        adst[i] = (uint32_t)(row * RS + c8 * 4) * 4;          // bytes
    }
    // B producer: 2 x 16B segs / thread / chunk (128 rows x 128B)
    const __half* pBb[2];
    uint32_t bdst[2];
#pragma unroll
    for (int i = 0; i < 2; i++) {
        int seg = i * 512 + tid;
        int row = seg >> 3, c8 = seg & 7;
        pBb[i] = (row < 64)
            ? (g_W0h + (size_t)(e * I_DIM + n0 + row) * D_DIM + c8 * 8)
            : (g_W1h + (size_t)(e * I_DIM + n0 + row - 64) * D_DIM + c8 * 8);
        bdst[i] = (uint32_t)(AU + row * RS + c8 * 4) * 4;
    }

    // ldmatrix lane-address components
    int a_row_off = (lane & 7) + ((lane >> 3) & 1) * 8;
    int a_word    = ((lane >> 4) & 1) * 4;
    int b_row_off = (lane & 7) + ((lane >> 4) & 1) * 8;
    int b_word    = ((lane >> 3) & 1) * 4;
    uint32_t aAddr[4], bAddr[2];
#pragma unroll
    for (int mi = 0; mi < 4; mi++)
        aAddr[mi] = sbase + (uint32_t)((wr * 64 + mi * 16 + a_row_off) * RS + a_word) * 4;
    bAddr[0] = sbase + (uint32_t)(AU + (16 * wc + b_row_off) * RS + b_word) * 4;
    bAddr[1] = sbase + (uint32_t)(AU + (64 + 16 * wc + b_row_off) * RS + b_word) * 4;

    float acc[4][4][4];
#pragma unroll
    for (int mi = 0; mi < 4; mi++)
#pragma unroll
        for (int ni = 0; ni < 4; ni++)
#pragma unroll
            for (int q = 0; q < 4; q++) acc[mi][ni][q] = 0.f;

    const int NCHUNK = D_DIM / BK;  // 32

#define G1_ISSUE(stg, chk) do {                                      \
        uint32_t so_ = (uint32_t)(stg) * (STAGE_U * 4);              \
        uint32_t ko_ = (uint32_t)(chk) * BK;                         \
        cpa16(sbase + so_ + adst[0], g_Xh + aoff[0] + ko_);          \
        cpa16(sbase + so_ + adst[1], g_Xh + aoff[1] + ko_);          \
        cpa16(sbase + so_ + adst[2], g_Xh + aoff[2] + ko_);          \
        cpa16(sbase + so_ + adst[3], g_Xh + aoff[3] + ko_);          \
        cpa16(sbase + so_ + bdst[0], pBb[0] + ko_);                  \
        cpa16(sbase + so_ + bdst[1], pBb[1] + ko_);                  \
        cp_commit();                                                 \
    } while (0)

    G1_ISSUE(0, 0);
    G1_ISSUE(1, 1);

    int stg = 0;
    for (int c = 0; c < NCHUNK; c++) {
        cp_wait1();
        __syncthreads();
        if (c + 2 < NCHUNK) {
            int ns = stg + 2; if (ns >= 3) ns -= 3;
            G1_ISSUE(ns, c + 2);
        }
        uint32_t so = (uint32_t)stg * (STAGE_U * 4);
#pragma unroll
        for (int s = 0; s < 4; s++) {       // four k16 steps per chunk
            uint32_t kb = s * 32;           // 8 words
            uint32_t a[4][4], b[4][2];
#pragma unroll
            for (int mi = 0; mi < 4; mi++)
                ldsm4(a[mi][0], a[mi][1], a[mi][2], a[mi][3], aAddr[mi] + so + kb);
            ldsm4(b[0][0], b[0][1], b[1][0], b[1][1], bAddr[0] + so + kb);
            ldsm4(b[2][0], b[2][1], b[3][0], b[3][1], bAddr[1] + so + kb);
#pragma unroll
            for (int mi = 0; mi < 4; mi++)
#pragma unroll
                for (int ni = 0; ni < 4; ni++)
                    mma16(acc[mi][ni], a[mi], b[ni]);
        }
        __syncthreads();
        if (++stg == 3) stg = 0;
    }

    // epilogue: H = silu(D0) * D1, store fp16 (pairs: ni and ni+2)
#pragma unroll
    for (int mi = 0; mi < 4; mi++) {
#pragma unroll
        for (int jj = 0; jj < 2; jj++) {
            int col = n0 + 16 * wc + 8 * jj + 2 * t;
            float* d0 = acc[mi][jj];
            float* d1 = acc[mi][jj + 2];
            int r0 = wr * 64 + mi * 16 + g;
            if (m0 + r0 < cnt) {
                float h0 = (d0[0] / (1.f + __expf(-d0[0]))) * d1[0];
                float h1 = (d0[1] / (1.f + __expf(-d0[1]))) * d1[1];
                *(uint32_t*)((__half*)g_H + (size_t)(base + m0 + r0) * I_DIM + col) = pk(h0, h1);
            }
            int r1 = r0 + 8;
            if (m0 + r1 < cnt) {
                float h0 = (d0[2] / (1.f + __expf(-d0[2]))) * d1[2];
                float h1 = (d0[3] / (1.f + __expf(-d0[3]))) * d1[3];
                *(uint32_t*)((__half*)g_H + (size_t)(base + m0 + r1) * I_DIM + col) = pk(h0, h1);
            }
        }
    }
}

// =====================================================================
// GEMM2: OUT[pair,:] = (H @ W2^T) * rw[pair].  Block 256x128, warp 64x32.
// =====================================================================
__global__ __launch_bounds__(512, 1)
void k_gemm2(const float* __restrict__ rw,
             float* __restrict__ out)
{
    extern __shared__ uint32_t sm[];
    __shared__ int rowPair[BM];

    int e   = blockIdx.z;
    int cnt = g_count[e];
    int m0  = blockIdx.y * BM;
    if (m0 >= cnt) return;
    int n0   = blockIdx.x * 128;
    int base = g_offset[e];

    int tid  = threadIdx.x;
    int wid  = tid >> 5;
    int lane = tid & 31;
    int g    = lane >> 2;
    int t    = lane & 3;
    int wr   = wid & 3;
    int wc   = wid >> 2;

    if (tid < BM) {
        int r = m0 + tid;
        rowPair[tid] = (r < cnt) ? g_pairs[base + r] : -1;
    }
    __syncthreads();

    uint32_t sbase = smem_u32(sm);

    // A producer from g_H: 4 x 16B segs / thread / chunk
    uint32_t aoff[4], adst[4];
#pragma unroll
    for (int i = 0; i < 4; i++) {
        int seg = i * 512 + tid;
        int row = seg >> 3, c8 = seg & 7;
        int grow = (m0 + row < cnt) ? (m0 + row) : m0;
        aoff[i] = (uint32_t)(base + grow) * I_DIM + c8 * 8;
        adst[i] = (uint32_t)(row * RS + c8 * 4) * 4;
    }
    // B producer from W2h: 2 x 16B segs / thread / chunk
    const __half* pBb[2];
    uint32_t bdst[2];
#pragma unroll
    for (int i = 0; i < 2; i++) {
        int seg = i * 512 + tid;
        int row = seg >> 3, c8 = seg & 7;
        pBb[i] = g_W2h + (size_t)(e * D_DIM + n0 + row) * I_DIM + c8 * 8;
        bdst[i] = (uint32_t)(AU + row * RS + c8 * 4) * 4;
    }

    int a_row_off = (lane & 7) + ((lane >> 3) & 1) * 8;
    int a_word    = ((lane >> 4) & 1) * 4;
    int b_row_off = (lane & 7) + ((lane >> 4) & 1) * 8;
    int b_word    = ((lane >> 3) & 1) * 4;
    uint32_t aAddr[4], bAddr[2];
#pragma unroll
    for (int mi = 0; mi < 4; mi++)
        aAddr[mi] = sbase + (uint32_t)((wr * 64 + mi * 16 + a_row_off) * RS + a_word) * 4;
    bAddr[0] = sbase + (uint32_t)(AU + (32 * wc + b_row_off) * RS + b_word) * 4;
    bAddr[1] = sbase + (uint32_t)(AU + (32 * wc + 16 + b_row_off) * RS + b_word) * 4;

    float acc[4][4][4];
#pragma unroll
    for (int mi = 0; mi < 4; mi++)
#pragma unroll
        for (int ni = 0; ni < 4; ni++)
#pragma unroll
            for (int q = 0; q < 4; q++) acc[mi][ni][q] = 0.f;

    const int NCHUNK = I_DIM / BK;  // 22

#define G2_ISSUE(stg, chk) do {                                      \
        uint32_t so_ = (uint32_t)(stg) * (STAGE_U * 4);              \
        uint32_t ko_ = (uint32_t)(chk) * BK;                         \
        cpa16(sbase + so_ + adst[0], (__half*)g_H + aoff[0] + ko_);  \
        cpa16(sbase + so_ + adst[1], (__half*)g_H + aoff[1] + ko_);  \
        cpa16(sbase + so_ + adst[2], (__half*)g_H + aoff[2] + ko_);  \
        cpa16(sbase + so_ + adst[3], (__half*)g_H + aoff[3] + ko_);  \
        cpa16(sbase + so_ + bdst[0], pBb[0] + ko_);                  \
        cpa16(sbase + so_ + bdst[1], pBb[1] + ko_);                  \
        cp_commit();                                                 \
    } while (0)

    G2_ISSUE(0, 0);
    G2_ISSUE(1, 1);

    int stg = 0;
    for (int c = 0; c < NCHUNK; c++) {
        cp_wait1();
        __syncthreads();
        if (c + 2 < NCHUNK) {
            int ns = stg + 2; if (ns >= 3) ns -= 3;
            G2_ISSUE(ns, c + 2);
        }
        uint32_t so = (uint32_t)stg * (STAGE_U * 4);
#pragma unroll
        for (int s = 0; s < 4; s++) {
            uint32_t kb = s * 32;
            uint32_t a[4][4], b[4][2];
#pragma unroll
            for (int mi = 0; mi < 4; mi++)
                ldsm4(a[mi][0], a[mi][1], a[mi][2], a[mi][3], aAddr[mi] + so + kb);
            ldsm4(b[0][0], b[0][1], b[1][0], b[1][1], bAddr[0] + so + kb);
            ldsm4(b[2][0], b[2][1], b[3][0], b[3][1], bAddr[1] + so + kb);
#pragma unroll
            for (int mi = 0; mi < 4; mi++)
#pragma unroll
                for (int ni = 0; ni < 4; ni++)
                    mma16(acc[mi][ni], a[mi], b[ni]);
        }
        __syncthreads();
        if (++stg == 3) stg = 0;
    }

    // epilogue: scale by routing weight, scatter to out[pair]
#pragma unroll
    for (int mi = 0; mi < 4; mi++) {
        int r0 = wr * 64 + mi * 16 + g;
#pragma unroll
        for (int half = 0; half < 2; half++) {
            int r = r0 + half * 8;
            if (m0 + r < cnt) {
                int pair = rowPair[r];
                float w  = rw[pair];
                float* op = out + (size_t)pair * D_DIM + n0;
#pragma unroll
                for (int ni = 0; ni < 4; ni++) {
                    int col = 32 * wc + 8 * ni + 2 * t;
                    float v0 = acc[mi][ni][half * 2 + 0] * w;
                    float v1 = acc[mi][ni][half * 2 + 1] * w;
                    *(float2*)(op + col) = make_float2(v0, v1);
                }
            }
        }
    }
}

// ---------------- launch ----------------
extern "C" void kernel_launch(void* const* d_in, const int* in_sizes, int n_in,
                              void* d_out, int out_size)
{
    const float* x   = (const float*)d_in[0];
    const float* w0  = (const float*)d_in[1];
    const float* w1  = (const float*)d_in[2];
    const float* w2  = (const float*)d_in[3];
    const int*   sel = (const int*)d_in[4];
    const float* rw  = (const float*)d_in[5];
    float* out = (float*)d_out;

    cudaFuncSetAttribute(k_gemm1, cudaFuncAttributeMaxDynamicSharedMemorySize, SMEM_B);
    cudaFuncSetAttribute(k_gemm2, cudaFuncAttributeMaxDynamicSharedMemorySize, SMEM_B);

    k_init<<<1, 32>>>();
    k_hist<<<NPAIR / 256, 256>>>(sel);
    k_scan<<<1, 1>>>();
    k_fill<<<NPAIR / 256, 256>>>(sel);

    // fused fp32 -> fp16 pre-conversion (W0, W1, W2, X in one launch)
    {
        __half *dW0h, *dW1h, *dW2h, *dXh;
        cudaGetSymbolAddress((void**)&dW0h, g_W0h);
        cudaGetSymbolAddress((void**)&dW1h, g_W1h);
        cudaGetSymbolAddress((void**)&dW2h, g_W2h);
        cudaGetSymbolAddress((void**)&dXh,  g_Xh);
        int tot4 = 3 * W4 + X4;
        k_cvt_all<<<(tot4 + 255) / 256, 256>>>(w0, w1, w2, x, dW0h, dW1h, dW2h, dXh);
    }

    dim3 g1(I_DIM / 64, T_TOK / BM, E_NUM);      // (22, 16, 16)
    k_gemm1<<<g1, 512, SMEM_B>>>();

    dim3 g2(D_DIM / 128, T_TOK / BM, E_NUM);     // (16, 16, 16)
    k_gemm2<<<g2, 512, SMEM_B>>>(rw, out);
}

// round 16
// speedup vs baseline: 10.8397x; 1.1575x over previous
#include <cuda_runtime.h>
#include <cuda_fp16.h>
#include <math.h>
#include <stdint.h>

// Problem constants
#define T_TOK 4096
#define D_DIM 2048
#define E_NUM 16
#define I_DIM 1408
#define K_TOP 4
#define NPAIR (T_TOK * K_TOP)   // 16384
#define WELEM (E_NUM * I_DIM * D_DIM)   // 46,137,344 per weight tensor

// -------- device scratch --------
__device__ int g_count[E_NUM];
__device__ int g_fill[E_NUM];
__device__ int g_offset[E_NUM + 1];
__device__ int g_pairs[NPAIR];
__device__ __half g_H[(size_t)NPAIR * I_DIM];     // 46 MB fp16 intermediate
__device__ __half g_W0h[WELEM];                   // 92 MB
__device__ __half g_W1h[WELEM];                   // 92 MB
__device__ __half g_W2h[WELEM];                   // 92 MB
__device__ __half g_Xh[(size_t)T_TOK * D_DIM];    // 16 MB

// ---------------- routing ----------------
__global__ void k_init() {
    int i = threadIdx.x;
    if (i < E_NUM) { g_count[i] = 0; g_fill[i] = 0; }
}
__global__ void k_hist(const int* __restrict__ sel) {
    int p = blockIdx.x * blockDim.x + threadIdx.x;
    if (p < NPAIR) atomicAdd(&g_count[sel[p]], 1);
}
__global__ void k_scan() {
    int acc = 0;
    for (int e = 0; e < E_NUM; e++) { g_offset[e] = acc; acc += g_count[e]; }
    g_offset[E_NUM] = acc;
}
__global__ void k_fill(const int* __restrict__ sel) {
    int p = blockIdx.x * blockDim.x + threadIdx.x;
    if (p < NPAIR) {
        int e = sel[p];
        int pos = g_offset[e] + atomicAdd(&g_fill[e], 1);
        g_pairs[pos] = p;
    }
}

// ---------------- helpers ----------------
__device__ __forceinline__ uint32_t pk(float lo, float hi) {
    uint32_t u;
    asm("cvt.rn.f16x2.f32 %0, %1, %2;" : "=r"(u) : "f"(hi), "f"(lo));
    return u;
}
__device__ __forceinline__ void mma16(float* d, const uint32_t* a, const uint32_t* b) {
    asm volatile(
        "mma.sync.aligned.m16n8k16.row.col.f32.f16.f16.f32 "
        "{%0,%1,%2,%3}, {%4,%5,%6,%7}, {%8,%9}, {%0,%1,%2,%3};"
        : "+f"(d[0]), "+f"(d[1]), "+f"(d[2]), "+f"(d[3])
        : "r"(a[0]), "r"(a[1]), "r"(a[2]), "r"(a[3]), "r"(b[0]), "r"(b[1]));
}
__device__ __forceinline__ void ldsm4(uint32_t& r0, uint32_t& r1, uint32_t& r2, uint32_t& r3,
                                      uint32_t saddr) {
    asm volatile("ldmatrix.sync.aligned.m8n8.x4.shared.b16 {%0,%1,%2,%3}, [%4];"
                 : "=r"(r0), "=r"(r1), "=r"(r2), "=r"(r3) : "r"(saddr));
}
__device__ __forceinline__ void cpa16(uint32_t saddr, const void* gaddr) {
    asm volatile("cp.async.cg.shared.global [%0], [%1], 16;" :: "r"(saddr), "l"(gaddr));
}
__device__ __forceinline__ void cp_commit() {
    asm volatile("cp.async.commit_group;" ::: "memory");
}
__device__ __forceinline__ void cp_wait1() {
    asm volatile("cp.async.wait_group 1;" ::: "memory");
}
__device__ __forceinline__ uint32_t smem_u32(const void* p) {
    uint32_t a;
    asm("{ .reg .u64 t; cvta.to.shared.u64 t, %1; cvt.u32.u64 %0, t; }" : "=r"(a) : "l"(p));
    return a;
}

// fused fp32 -> fp16 conversion of W0, W1, W2, X in one launch
#define W4 (WELEM / 4)                      // 11,534,336 float4 groups
#define X4 ((T_TOK * D_DIM) / 4)            // 2,097,152
__global__ __launch_bounds__(256) void k_cvt_all(
    const float* __restrict__ w0, const float* __restrict__ w1,
    const float* __restrict__ w2, const float* __restrict__ x,
    __half* __restrict__ dw0, __half* __restrict__ dw1,
    __half* __restrict__ dw2, __half* __restrict__ dx)
{
    int i = blockIdx.x * blockDim.x + threadIdx.x;
    const float* s; __half* d; int j;
    if (i < W4)            { s = w0; d = dw0; j = i; }
    else if (i < 2 * W4)   { s = w1; d = dw1; j = i - W4; }
    else if (i < 3 * W4)   { s = w2; d = dw2; j = i - 2 * W4; }
    else if (i < 3 * W4 + X4) { s = x; d = dx; j = i - 3 * W4; }
    else return;
    float4 v = ((const float4*)s)[j];
    ((uint2*)d)[j] = make_uint2(pk(v.x, v.y), pk(v.z, v.w));
}

// ---------------- tiling ----------------
#define BM   128
#define BK   64                         // K halves per chunk (4 x k16 steps) = 128B/row
#define RS   36                         // smem row stride in b32 (32 data + 4 pad)
#define AU   (128 * RS)                 // A region b32 per stage = 4608
#define BU   (128 * RS)                 // B region b32 per stage = 4608
#define STAGE_U (AU + BU)               // 9216 b32 = 36 KB
#define STAGES 3
#define SMEM_B  (STAGES * STAGE_U * 4)  // 110,592 bytes dynamic (2 CTAs/SM)

// =====================================================================
// GEMM1: D0 = X@W0^T, D1 = X@W1^T (shared X), H = silu(D0)*D1  [fp16]
// Block: 128 rows x 64 I-cols. B smem = [W0h 64 rows | W1h 64 rows].
// 8 warps: wr=wid&1 (64-row half), wc=wid>>1 (16-col group). 2 CTAs/SM.
// BK=64, 3-stage cp.async ring, single barrier per chunk.
// IMPORTANT: cp_commit is UNCONDITIONAL each iteration (empty groups at the
// tail keep the wait_group accounting correct so the last chunk is waited on).
// =====================================================================
__global__ __launch_bounds__(256, 2)
void k_gemm1()
{
    extern __shared__ uint32_t sm[];
    __shared__ int rowTok[BM];

    int e   = blockIdx.z;
    int cnt = g_count[e];
    int m0  = blockIdx.y * BM;
    if (m0 >= cnt) return;
    int n0   = blockIdx.x * 64;
    int base = g_offset[e];

    int tid  = threadIdx.x;
    int wid  = tid >> 5;
    int lane = tid & 31;
    int g    = lane >> 2;
    int t    = lane & 3;
    int wr   = wid & 1;
    int wc   = wid >> 1;

    if (tid < BM) {
        int r = m0 + tid;
        rowTok[tid] = (r < cnt) ? (g_pairs[base + r] / K_TOP) : -1;
    }
    __syncthreads();

    uint32_t sbase = smem_u32(sm);

    // A producer: 4 x 16B segs / thread / chunk (128 rows x 128B)
    uint32_t aoff[4], adst[4];
#pragma unroll
    for (int i = 0; i < 4; i++) {
        int seg = i * 256 + tid;
        int row = seg >> 3, c8 = seg & 7;
        int tok = rowTok[row];
        if (tok < 0) tok = 0;
        aoff[i] = (uint32_t)tok * D_DIM + c8 * 8;             // halves
        adst[i] = (uint32_t)(row * RS + c8 * 4) * 4;          // bytes
    }
    // B producer: 4 x 16B segs / thread / chunk (128 rows x 128B)
    const __half* pBb[4];
    uint32_t bdst[4];
#pragma unroll
    for (int i = 0; i < 4; i++) {
        int seg = i * 256 + tid;
        int row = seg >> 3, c8 = seg & 7;
        pBb[i] = (row < 64)
            ? (g_W0h + (size_t)(e * I_DIM + n0 + row) * D_DIM + c8 * 8)
            : (g_W1h + (size_t)(e * I_DIM + n0 + row - 64) * D_DIM + c8 * 8);
        bdst[i] = (uint32_t)(AU + row * RS + c8 * 4) * 4;
    }

    // ldmatrix lane-address components
    int a_row_off = (lane & 7) + ((lane >> 3) & 1) * 8;
    int a_word    = ((lane >> 4) & 1) * 4;
    int b_row_off = (lane & 7) + ((lane >> 4) & 1) * 8;
    int b_word    = ((lane >> 3) & 1) * 4;
    uint32_t aAddr[4], bAddr[2];
#pragma unroll
    for (int mi = 0; mi < 4; mi++)
        aAddr[mi] = sbase + (uint32_t)((wr * 64 + mi * 16 + a_row_off) * RS + a_word) * 4;
    bAddr[0] = sbase + (uint32_t)(AU + (16 * wc + b_row_off) * RS + b_word) * 4;
    bAddr[1] = sbase + (uint32_t)(AU + (64 + 16 * wc + b_row_off) * RS + b_word) * 4;

    float acc[4][4][4];
#pragma unroll
    for (int mi = 0; mi < 4; mi++)
#pragma unroll
        for (int ni = 0; ni < 4; ni++)
#pragma unroll
            for (int q = 0; q < 4; q++) acc[mi][ni][q] = 0.f;

    const int NCHUNK = D_DIM / BK;  // 32

#define G1_ISSUE(stg, chk) do {                                      \
        uint32_t so_ = (uint32_t)(stg) * (STAGE_U * 4);              \
        uint32_t ko_ = (uint32_t)(chk) * BK;                         \
        cpa16(sbase + so_ + adst[0], g_Xh + aoff[0] + ko_);          \
        cpa16(sbase + so_ + adst[1], g_Xh + aoff[1] + ko_);          \
        cpa16(sbase + so_ + adst[2], g_Xh + aoff[2] + ko_);          \
        cpa16(sbase + so_ + adst[3], g_Xh + aoff[3] + ko_);          \
        cpa16(sbase + so_ + bdst[0], pBb[0] + ko_);                  \
        cpa16(sbase + so_ + bdst[1], pBb[1] + ko_);                  \
        cpa16(sbase + so_ + bdst[2], pBb[2] + ko_);                  \
        cpa16(sbase + so_ + bdst[3], pBb[3] + ko_);                  \
    } while (0)

    G1_ISSUE(0, 0); cp_commit();
    G1_ISSUE(1, 1); cp_commit();

    int stg = 0;
    for (int c = 0; c < NCHUNK; c++) {
        cp_wait1();
        // Single rendezvous per chunk: on arrival, every warp has finished
        // reading stage (c-1)%3, so issuing chunk c+2 into that stage is safe.
        __syncthreads();
        if (c + 2 < NCHUNK) {
            int ns = stg + 2; if (ns >= 3) ns -= 3;
            G1_ISSUE(ns, c + 2);
        }
        cp_commit();   // unconditional: empty groups keep tail waits honest
        uint32_t so = (uint32_t)stg * (STAGE_U * 4);
#pragma unroll
        for (int s = 0; s < 4; s++) {       // four k16 steps per chunk
            uint32_t kb = s * 32;           // 8 words
            uint32_t a[4][4], b[4][2];
#pragma unroll
            for (int mi = 0; mi < 4; mi++)
                ldsm4(a[mi][0], a[mi][1], a[mi][2], a[mi][3], aAddr[mi] + so + kb);
            ldsm4(b[0][0], b[0][1], b[1][0], b[1][1], bAddr[0] + so + kb);
            ldsm4(b[2][0], b[2][1], b[3][0], b[3][1], bAddr[1] + so + kb);
#pragma unroll
            for (int mi = 0; mi < 4; mi++)
#pragma unroll
                for (int ni = 0; ni < 4; ni++)
                    mma16(acc[mi][ni], a[mi], b[ni]);
        }
        if (++stg == 3) stg = 0;
    }

    // epilogue: H = silu(D0) * D1, store fp16 (pairs: ni and ni+2)
#pragma unroll
    for (int mi = 0; mi < 4; mi++) {
#pragma unroll
        for (int jj = 0; jj < 2; jj++) {
            int col = n0 + 16 * wc + 8 * jj + 2 * t;
            float* d0 = acc[mi][jj];
            float* d1 = acc[mi][jj + 2];
            int r0 = wr * 64 + mi * 16 + g;
            if (m0 + r0 < cnt) {
                float h0 = (d0[0] / (1.f + __expf(-d0[0]))) * d1[0];
                float h1 = (d0[1] / (1.f + __expf(-d0[1]))) * d1[1];
                *(uint32_t*)((__half*)g_H + (size_t)(base + m0 + r0) * I_DIM + col) = pk(h0, h1);
            }
            int r1 = r0 + 8;
            if (m0 + r1 < cnt) {
                float h0 = (d0[2] / (1.f + __expf(-d0[2]))) * d1[2];
                float h1 = (d0[3] / (1.f + __expf(-d0[3]))) * d1[3];
                *(uint32_t*)((__half*)g_H + (size_t)(base + m0 + r1) * I_DIM + col) = pk(h0, h1);
            }
        }
    }
}

// =====================================================================
// GEMM2: OUT[pair,:] = (H @ W2^T) * rw[pair].  Block 128x128, warp 64x32.
// 2 CTAs/SM, single barrier per chunk, unconditional commit (tail fix).
// =====================================================================
__global__ __launch_bounds__(256, 2)
void k_gemm2(const float* __restrict__ rw,
             float* __restrict__ out)
{
    extern __shared__ uint32_t sm[];
    __shared__ int rowPair[BM];

    int e   = blockIdx.z;
    int cnt = g_count[e];
    int m0  = blockIdx.y * BM;
    if (m0 >= cnt) return;
    int n0   = blockIdx.x * 128;
    int base = g_offset[e];

    int tid  = threadIdx.x;
    int wid  = tid >> 5;
    int lane = tid & 31;
    int g    = lane >> 2;
    int t    = lane & 3;
    int wr   = wid & 1;
    int wc   = wid >> 1;

    if (tid < BM) {
        int r = m0 + tid;
        rowPair[tid] = (r < cnt) ? g_pairs[base + r] : -1;
    }
    __syncthreads();

    uint32_t sbase = smem_u32(sm);

    // A producer from g_H: 4 x 16B segs / thread / chunk
    uint32_t aoff[4], adst[4];
#pragma unroll
    for (int i = 0; i < 4; i++) {
        int seg = i * 256 + tid;
        int row = seg >> 3, c8 = seg & 7;
        int grow = (m0 + row < cnt) ? (m0 + row) : m0;
        aoff[i] = (uint32_t)(base + grow) * I_DIM + c8 * 8;
        adst[i] = (uint32_t)(row * RS + c8 * 4) * 4;
    }
    // B producer from W2h: 4 x 16B segs / thread / chunk
    const __half* pBb[4];
    uint32_t bdst[4];
#pragma unroll
    for (int i = 0; i < 4; i++) {
        int seg = i * 256 + tid;
        int row = seg >> 3, c8 = seg & 7;
        pBb[i] = g_W2h + (size_t)(e * D_DIM + n0 + row) * I_DIM + c8 * 8;
        bdst[i] = (uint32_t)(AU + row * RS + c8 * 4) * 4;
    }

    int a_row_off = (lane & 7) + ((lane >> 3) & 1) * 8;
    int a_word    = ((lane >> 4) & 1) * 4;
    int b_row_off = (lane & 7) + ((lane >> 4) & 1) * 8;
    int b_word    = ((lane >> 3) & 1) * 4;
    uint32_t aAddr[4], bAddr[2];
#pragma unroll
    for (int mi = 0; mi < 4; mi++)
        aAddr[mi] = sbase + (uint32_t)((wr * 64 + mi * 16 + a_row_off) * RS + a_word) * 4;
    bAddr[0] = sbase + (uint32_t)(AU + (32 * wc + b_row_off) * RS + b_word) * 4;
    bAddr[1] = sbase + (uint32_t)(AU + (32 * wc + 16 + b_row_off) * RS + b_word) * 4;

    float acc[4][4][4];
#pragma unroll
    for (int mi = 0; mi < 4; mi++)
#pragma unroll
        for (int ni = 0; ni < 4; ni++)
#pragma unroll
            for (int q = 0; q < 4; q++) acc[mi][ni][q] = 0.f;

    const int NCHUNK = I_DIM / BK;  // 22

#define G2_ISSUE(stg, chk) do {                                      \
        uint32_t so_ = (uint32_t)(stg) * (STAGE_U * 4);              \
        uint32_t ko_ = (uint32_t)(chk) * BK;                         \
        cpa16(sbase + so_ + adst[0], (__half*)g_H + aoff[0] + ko_);  \
        cpa16(sbase + so_ + adst[1], (__half*)g_H + aoff[1] + ko_);  \
        cpa16(sbase + so_ + adst[2], (__half*)g_H + aoff[2] + ko_);  \
        cpa16(sbase + so_ + adst[3], (__half*)g_H + aoff[3] + ko_);  \
        cpa16(sbase + so_ + bdst[0], pBb[0] + ko_);                  \
        cpa16(sbase + so_ + bdst[1], pBb[1] + ko_);                  \
        cpa16(sbase + so_ + bdst[2], pBb[2] + ko_);                  \
        cpa16(sbase + so_ + bdst[3], pBb[3] + ko_);                  \
    } while (0)

    G2_ISSUE(0, 0); cp_commit();
    G2_ISSUE(1, 1); cp_commit();

    int stg = 0;
    for (int c = 0; c < NCHUNK; c++) {
        cp_wait1();
        __syncthreads();
        if (c + 2 < NCHUNK) {
            int ns = stg + 2; if (ns >= 3) ns -= 3;
            G2_ISSUE(ns, c + 2);
        }
        cp_commit();   // unconditional: empty groups keep tail waits honest
        uint32_t so = (uint32_t)stg * (STAGE_U * 4);
#pragma unroll
        for (int s = 0; s < 4; s++) {
            uint32_t kb = s * 32;
            uint32_t a[4][4], b[4][2];
#pragma unroll
            for (int mi = 0; mi < 4; mi++)
                ldsm4(a[mi][0], a[mi][1], a[mi][2], a[mi][3], aAddr[mi] + so + kb);
            ldsm4(b[0][0], b[0][1], b[1][0], b[1][1], bAddr[0] + so + kb);
            ldsm4(b[2][0], b[2][1], b[3][0], b[3][1], bAddr[1] + so + kb);
#pragma unroll
            for (int mi = 0; mi < 4; mi++)
#pragma unroll
                for (int ni = 0; ni < 4; ni++)
                    mma16(acc[mi][ni], a[mi], b[ni]);
        }
        if (++stg == 3) stg = 0;
    }

    // epilogue: scale by routing weight, scatter to out[pair]
#pragma unroll
    for (int mi = 0; mi < 4; mi++) {
        int r0 = wr * 64 + mi * 16 + g;
#pragma unroll
        for (int half = 0; half < 2; half++) {
            int r = r0 + half * 8;
            if (m0 + r < cnt) {
                int pair = rowPair[r];
                float w  = rw[pair];
                float* op = out + (size_t)pair * D_DIM + n0;
#pragma unroll
                for (int ni = 0; ni < 4; ni++) {
                    int col = 32 * wc + 8 * ni + 2 * t;
                    float v0 = acc[mi][ni][half * 2 + 0] * w;
                    float v1 = acc[mi][ni][half * 2 + 1] * w;
                    *(float2*)(op + col) = make_float2(v0, v1);
                }
            }
        }
    }
}

// ---------------- launch ----------------
extern "C" void kernel_launch(void* const* d_in, const int* in_sizes, int n_in,
                              void* d_out, int out_size)
{
    const float* x   = (const float*)d_in[0];
    const float* w0  = (const float*)d_in[1];
    const float* w1  = (const float*)d_in[2];
    const float* w2  = (const float*)d_in[3];
    const int*   sel = (const int*)d_in[4];
    const float* rw  = (const float*)d_in[5];
    float* out = (float*)d_out;

    cudaFuncSetAttribute(k_gemm1, cudaFuncAttributeMaxDynamicSharedMemorySize, SMEM_B);
    cudaFuncSetAttribute(k_gemm2, cudaFuncAttributeMaxDynamicSharedMemorySize, SMEM_B);

    k_init<<<1, 32>>>();
    k_hist<<<NPAIR / 256, 256>>>(sel);
    k_scan<<<1, 1>>>();
    k_fill<<<NPAIR / 256, 256>>>(sel);

    // fused fp32 -> fp16 pre-conversion (W0, W1, W2, X in one launch)
    {
        __half *dW0h, *dW1h, *dW2h, *dXh;
        cudaGetSymbolAddress((void**)&dW0h, g_W0h);
        cudaGetSymbolAddress((void**)&dW1h, g_W1h);
        cudaGetSymbolAddress((void**)&dW2h, g_W2h);
        cudaGetSymbolAddress((void**)&dXh,  g_Xh);
        int tot4 = 3 * W4 + X4;
        k_cvt_all<<<(tot4 + 255) / 256, 256>>>(w0, w1, w2, x, dW0h, dW1h, dW2h, dXh);
    }

    dim3 g1(I_DIM / 64, T_TOK / BM, E_NUM);      // (22, 32, 16)
    k_gemm1<<<g1, 256, SMEM_B>>>();

    dim3 g2(D_DIM / 128, T_TOK / BM, E_NUM);     // (16, 32, 16)
    k_gemm2<<<g2, 256, SMEM_B>>>(rw, out);
}